// round 11
// baseline (speedup 1.0000x reference)
#include <cuda_runtime.h>
#include <cuda_bf16.h>
#include <cstdint>

#define BATCH 32
#define HID   256
#define VOCAB 10000
#define STEPS 256

// ---------------- config ----------------
#define CLUSTER 4
#define BPC     2
#define DPC     64
#define NREC    64                 // recurrence CTAs (bids 0..63, wave 1)
#define FTH     256                // threads per CTA (fused kernel)

#define GBM 128
#define GBN 128
#define GBK 16
#define GNC (HID / GBK)
#define NTN ((VOCAB + GBN - 1) / GBN)   // 79 N tiles
#define NTM ((STEPS * BATCH) / GBM)     // 64 M tiles

// ---------------- scratch (device globals: allocation-free) ----------------
__device__ __nv_bfloat16 g_Ahi[STEPS * BATCH * HID];
__device__ __nv_bfloat16 g_Alo[STEPS * BATCH * HID];
__device__ __nv_bfloat16 g_Bhi[HID * VOCAB];
__device__ __nv_bfloat16 g_Blo[HID * VOCAB];
__device__ unsigned g_prog[NREC];   // per-recurrence-CTA step progress (t+1)

__global__ void prog_reset_kernel() {
    if (threadIdx.x < NREC) g_prog[threadIdx.x] = 0u;
}

__global__ void convB_kernel(const float* __restrict__ W) {
    int i = blockIdx.x * 256 + threadIdx.x;
    if (i < HID * VOCAB) {
        float v = W[i];
        __nv_bfloat16 h = __float2bfloat16(v);
        g_Bhi[i] = h;
        g_Blo[i] = __float2bfloat16(v - __bfloat162float(h));
    }
}

__device__ __forceinline__ uint32_t sptr(const void* p) {
    return (uint32_t)__cvta_generic_to_shared(p);
}
__device__ __forceinline__ unsigned ld_acq(const unsigned* p) {
    unsigned v;
    asm volatile("ld.acquire.gpu.global.u32 %0, [%1];" : "=r"(v) : "l"(p) : "memory");
    return v;
}
__device__ __forceinline__ void st_rel(unsigned* p, unsigned v) {
    asm volatile("st.release.gpu.global.u32 [%0], %1;" :: "l"(p), "r"(v) : "memory");
}

#define FMA2(acc, a, b) \
    asm("fma.rn.f32x2 %0, %1, %2, %0;" : "+l"(acc) : "l"(a), "l"(b))

__device__ __forceinline__ float2 unpack2(unsigned long long v) {
    float2 f;
    asm("mov.b64 {%0, %1}, %2;" : "=f"(f.x), "=f"(f.y) : "l"(v));
    return f;
}

__device__ __forceinline__ void st_cluster_f32(uint32_t laddr, int rank, float v) {
    uint32_t ra;
    asm("mapa.shared::cluster.u32 %0, %1, %2;" : "=r"(ra) : "r"(laddr), "r"(rank));
    asm volatile("st.shared::cluster.f32 [%0], %1;" :: "r"(ra), "f"(v) : "memory");
}

#define CLUSTER_SYNC() do { \
    asm volatile("barrier.cluster.arrive.aligned;" ::: "memory"); \
    asm volatile("barrier.cluster.wait.aligned;"   ::: "memory"); \
} while (0)

// ---- mbarrier helpers (DSMEM sync, no L1D flush) ----
__device__ __forceinline__ void mbar_init(uint32_t addr, uint32_t cnt) {
    asm volatile("mbarrier.init.shared.b64 [%0], %1;" :: "r"(addr), "r"(cnt) : "memory");
}
// release-arrive on CTA `rank`'s barrier at the same smem offset
__device__ __forceinline__ void mbar_arrive_cluster(uint32_t laddr, uint32_t rank) {
    uint32_t ra;
    asm("mapa.shared::cluster.u32 %0, %1, %2;" : "=r"(ra) : "r"(laddr), "r"(rank));
    asm volatile("mbarrier.arrive.release.cluster.shared::cluster.b64 _, [%0];"
                 :: "r"(ra) : "memory");
}
// acquire (cluster-scope) parity wait on the local barrier
__device__ __forceinline__ void mbar_wait(uint32_t addr, unsigned parity) {
    unsigned done;
    do {
        asm volatile(
            "{\n\t.reg .pred p;\n\t"
            "mbarrier.try_wait.parity.acquire.cluster.shared::cta.b64 p, [%1], %2;\n\t"
            "selp.b32 %0, 1, 0, p;\n\t}"
            : "=r"(done) : "r"(addr), "r"(parity) : "memory");
    } while (!done);
}

// ---------------- smem overlays (one dynamic buffer) ----------------
struct RSmem {                           // recurrence CTAs
    float4 Wq[3][HID / 4][DPC];          // 196608 B
    float4 hq[BPC][HID / 4];
    float4 rhq[BPC][HID / 4];
    unsigned long long mbar[2];          // [0]=rh exchange, [1]=h exchange
};
struct GSmem {                           // GEMM CTAs (32 KB region of same buffer)
    __nv_bfloat16 Ah[2][GBM * GBK];
    __nv_bfloat16 Al[2][GBM * GBK];
    __nv_bfloat16 Bh[2][GBK * GBN];
    __nv_bfloat16 Bl[2][GBK * GBN];
};

extern __shared__ __align__(16) char dyn_smem[];

// ================= recurrence body (mbarrier-synced, tid<128 active) =================
__device__ void rnn_body(const int* __restrict__ X, const float* __restrict__ H0,
                         const float* __restrict__ Wxz, const float* __restrict__ Whz, const float* __restrict__ bz,
                         const float* __restrict__ Wxr, const float* __restrict__ Whr, const float* __restrict__ br,
                         const float* __restrict__ Wxh, const float* __restrict__ Whh, const float* __restrict__ bh,
                         float* __restrict__ outF)
{
    RSmem* s = reinterpret_cast<RSmem*>(dyn_smem);
    const int tid    = threadIdx.x;
    const bool active = tid < 128;
    const int rank = (int)(blockIdx.x & (CLUSTER - 1));
    const int cid  = (int)(blockIdx.x >> 2);
    const int dim0 = rank * DPC;
    const int b    = tid & 1;
    const int d    = active ? (tid >> 1) : 0;
    const int bg   = cid * BPC + b;
    const int dim  = dim0 + d;

    // one-time weight slice load (all 256 threads help)
    for (int i = tid; i < 3 * (HID / 4) * DPC; i += FTH) {
        int g  = i / ((HID / 4) * DPC);
        int r  = i % ((HID / 4) * DPC);
        int kq = r / DPC;
        int dd = r % DPC;
        const float* W = (g == 0) ? Whz : ((g == 1) ? Whr : Whh);
        float4 v;
        v.x = W[(kq * 4 + 0) * HID + dim0 + dd];
        v.y = W[(kq * 4 + 1) * HID + dim0 + dd];
        v.z = W[(kq * 4 + 2) * HID + dim0 + dd];
        v.w = W[(kq * 4 + 3) * HID + dim0 + dd];
        s->Wq[g][kq][dd] = v;
    }
    if (tid < BPC * (HID / 4)) {
        int bb = tid >> 6;
        int kq = tid & 63;
        s->hq[bb][kq] = *reinterpret_cast<const float4*>(&H0[(cid * BPC + bb) * HID + kq * 4]);
    }
    const uint32_t mb0 = sptr(&s->mbar[0]);
    const uint32_t mb1 = sptr(&s->mbar[1]);
    if (tid == 0) {
        mbar_init(mb0, CLUSTER);
        mbar_init(mb1, CLUSTER);
    }
    const float bzv = bz[dim];
    const float brv = br[dim];
    const float bhv = bh[dim];
    __syncthreads();
    CLUSTER_SYNC();   // guards mbarrier init + initial h visibility (once, off hot loop)

    const uint32_t rh_addr = sptr(&reinterpret_cast<float*>(s->rhq)[b * HID + dim]);
    const uint32_t h_addr  = sptr(&reinterpret_cast<float*>(s->hq)[b * HID + dim]);

    unsigned parity = 0;

    #pragma unroll 1
    for (int t = 0; t < STEPS; ++t) {
        float zv = 0.f, hold = 0.f, xh = 0.f;   // carried in registers across sync

        if (active) {
            int   xv = X[bg * STEPS + t];
            float xz = Wxz[xv * HID + dim];
            float xr = Wxr[xv * HID + dim];
            xh   = Wxh[xv * HID + dim];          // prefetched; LDG overlaps phase-1 math
            hold = reinterpret_cast<const float*>(s->hq)[b * HID + dim];

            unsigned long long az0 = 0ull, az1 = 0ull, ar0 = 0ull, ar1 = 0ull;
            const ulonglong2* wz = reinterpret_cast<const ulonglong2*>(&s->Wq[0][0][d]);
            const ulonglong2* wr = reinterpret_cast<const ulonglong2*>(&s->Wq[1][0][d]);
            const ulonglong2* hp = reinterpret_cast<const ulonglong2*>(&s->hq[b][0]);
            #pragma unroll 16
            for (int kq = 0; kq < HID / 4; ++kq) {
                ulonglong2 h2 = hp[kq];
                ulonglong2 a  = wz[kq * DPC];
                ulonglong2 c  = wr[kq * DPC];
                FMA2(az0, a.x, h2.x); FMA2(az1, a.y, h2.y);
                FMA2(ar0, c.x, h2.x); FMA2(ar1, c.y, h2.y);
            }
            float2 z0 = unpack2(az0), z1 = unpack2(az1);
            float2 r0 = unpack2(ar0), r1 = unpack2(ar1);
            zv = 1.f / (1.f + expf(-(((z0.x + z0.y) + (z1.x + z1.y)) + xz + bzv)));
            float rv = 1.f / (1.f + expf(-(((r0.x + r0.y) + (r1.x + r1.y)) + xr + brv)));
            float rh = rv * hold;
            #pragma unroll
            for (int rr = 0; rr < CLUSTER; ++rr) st_cluster_f32(rh_addr, rr, rh);
        }
        // ---- rh exchange: bar.sync orders all stores; release-arrive publishes ----
        __syncthreads();
        if (tid == 0) {
            #pragma unroll
            for (int rr = 0; rr < CLUSTER; ++rr) mbar_arrive_cluster(mb0, rr);
        }
        mbar_wait(mb0, parity);

        if (active) {
            unsigned long long ah0 = 0ull, ah1 = 0ull;
            const ulonglong2* wh = reinterpret_cast<const ulonglong2*>(&s->Wq[2][0][d]);
            const ulonglong2* rp = reinterpret_cast<const ulonglong2*>(&s->rhq[b][0]);
            #pragma unroll 16
            for (int kq = 0; kq < HID / 4; ++kq) {
                ulonglong2 r2 = rp[kq];
                ulonglong2 a  = wh[kq * DPC];
                FMA2(ah0, a.x, r2.x); FMA2(ah1, a.y, r2.y);
            }
            float2 h0 = unpack2(ah0), h1 = unpack2(ah1);
            float htl  = tanhf(((h0.x + h0.y) + (h1.x + h1.y)) + xh + bhv);
            float hnew = zv * hold + (1.f - zv) * htl;
            #pragma unroll
            for (int rr = 0; rr < CLUSTER; ++rr) st_cluster_f32(h_addr, rr, hnew);

            int row = t * BATCH + bg;
            __nv_bfloat16 hb = __float2bfloat16(hnew);
            g_Ahi[row * HID + dim] = hb;
            g_Alo[row * HID + dim] = __float2bfloat16(hnew - __bfloat162float(hb));
            if (t == STEPS - 1) outF[bg * HID + dim] = hnew;
        }
        // ---- h exchange + progress publication ----
        __syncthreads();
        if (tid == 0) {
            #pragma unroll
            for (int rr = 0; rr < CLUSTER; ++rr) mbar_arrive_cluster(mb1, rr);
            st_rel(&g_prog[blockIdx.x], (unsigned)(t + 1));   // covers g_Ahi via bar.sync hb
        }
        mbar_wait(mb1, parity);
        parity ^= 1u;
    }
}

// ================= GEMM body (round-3 logic, smem from dynamic buffer) =================
#define CP16(dst, src, sz) \
    asm volatile("cp.async.cg.shared.global [%0], [%1], 16, %2;" :: "r"(dst), "l"(src), "r"(sz))
#define LDSM4(r, addr) \
    asm volatile("ldmatrix.sync.aligned.m8n8.x4.shared.b16 {%0,%1,%2,%3}, [%4];" \
        : "=r"((r)[0]), "=r"((r)[1]), "=r"((r)[2]), "=r"((r)[3]) : "r"(addr))
#define LDSMT2(r, addr) \
    asm volatile("ldmatrix.sync.aligned.m8n8.x2.trans.shared.b16 {%0,%1}, [%2];" \
        : "=r"((r)[0]), "=r"((r)[1]) : "r"(addr))
#define MMA16816(d, a, b) \
    asm volatile("mma.sync.aligned.m16n8k16.row.col.f32.bf16.bf16.f32 " \
        "{%0,%1,%2,%3}, {%4,%5,%6,%7}, {%8,%9}, {%0,%1,%2,%3};" \
        : "+f"((d)[0]), "+f"((d)[1]), "+f"((d)[2]), "+f"((d)[3]) \
        : "r"((a)[0]), "r"((a)[1]), "r"((a)[2]), "r"((a)[3]), "r"((b)[0]), "r"((b)[1]))

__device__ void gemm_body(int g, const float* __restrict__ bias, float* __restrict__ C)
{
    GSmem* gs = reinterpret_cast<GSmem*>(dyn_smem);
    const int tid  = threadIdx.x;
    const int lane = tid & 31;
    const int warp = tid >> 5;
    const int wm   = (warp >> 2) * 64;
    const int wn   = (warp & 3) * 32;
    const int mtile = g / NTN;
    const int ntile = g % NTN;
    const int m0   = mtile * GBM;
    const int n0   = ntile * GBN;

    // ---- band wait: all 64 recurrence CTAs past step 4*mtile+3 ----
    const unsigned need = (unsigned)(mtile * 4 + 4);
    if (tid < NREC) {
        while (ld_acq(&g_prog[tid]) < need) __nanosleep(256);
    }
    __syncthreads();

    float acc[4][4][4];
    #pragma unroll
    for (int i = 0; i < 4; ++i)
        #pragma unroll
        for (int j = 0; j < 4; ++j)
            #pragma unroll
            for (int q = 0; q < 4; ++q) acc[i][j][q] = 0.f;

    auto load_stage = [&](int st, int k0) {
        #pragma unroll
        for (int i = 0; i < 2; ++i) {
            int idx = tid + (i << 8);
            int sel = idx >> 8;
            int r   = idx & 255;
            int m   = r >> 1;
            int ku  = r & 1;
            const __nv_bfloat16* gp = (sel ? g_Alo : g_Ahi) + (size_t)(m0 + m) * HID + k0 + ku * 8;
            uint32_t dd = sptr(sel ? gs->Al[st] : gs->Ah[st]) + m * 32 + ((ku ^ ((m >> 2) & 1)) << 4);
            CP16(dd, gp, 16);
        }
        #pragma unroll
        for (int i = 0; i < 2; ++i) {
            int idx = tid + (i << 8);
            int sel = idx >> 8;
            int r   = idx & 255;
            int k   = r >> 4;
            int nu  = r & 15;
            int col = n0 + nu * 8;
            const __nv_bfloat16* gp = (sel ? g_Blo : g_Bhi) + (size_t)(k0 + k) * VOCAB + col;
            uint32_t dd = sptr(sel ? gs->Bl[st] : gs->Bh[st]) + k * 256 + ((nu ^ (k & 7)) << 4);
            int sz = (col + 8 <= VOCAB) ? 16 : 0;
            CP16(dd, gp, sz);
        }
    };

    load_stage(0, 0);
    asm volatile("cp.async.commit_group;");

    const int lrow = lane & 15;
    const int lkb  = (lane >> 4) & 1;

    #pragma unroll 1
    for (int c = 0; c < GNC; ++c) {
        if (c + 1 < GNC) load_stage((c + 1) & 1, (c + 1) * GBK);
        asm volatile("cp.async.commit_group;");
        asm volatile("cp.async.wait_group 1;");
        __syncthreads();

        const int st = c & 1;
        uint32_t ah[4][4], al[4][4], bh[4][2], bl[4][2];
        #pragma unroll
        for (int mt = 0; mt < 4; ++mt) {
            int m = wm + mt * 16 + lrow;
            uint32_t off = m * 32 + ((lkb ^ ((m >> 2) & 1)) << 4);
            LDSM4(ah[mt], sptr(gs->Ah[st]) + off);
            LDSM4(al[mt], sptr(gs->Al[st]) + off);
        }
        #pragma unroll
        for (int nt = 0; nt < 4; ++nt) {
            int k = lrow;
            int n = wn + nt * 8;
            uint32_t off = k * 256 + (((n >> 3) ^ (k & 7)) << 4);
            LDSMT2(bh[nt], sptr(gs->Bh[st]) + off);
            LDSMT2(bl[nt], sptr(gs->Bl[st]) + off);
        }
        #pragma unroll
        for (int mt = 0; mt < 4; ++mt)
            #pragma unroll
            for (int nt = 0; nt < 4; ++nt) {
                MMA16816(acc[mt][nt], ah[mt], bh[nt]);
                MMA16816(acc[mt][nt], ah[mt], bl[nt]);
                MMA16816(acc[mt][nt], al[mt], bh[nt]);
            }
        __syncthreads();
    }

    #pragma unroll
    for (int nt = 0; nt < 4; ++nt) {
        int cbase = n0 + wn + nt * 8 + 2 * (lane & 3);
        float2 bv = make_float2(0.f, 0.f);
        if (cbase + 1 < VOCAB) bv = *reinterpret_cast<const float2*>(bias + cbase);
        #pragma unroll
        for (int mt = 0; mt < 4; ++mt) {
            int r0 = m0 + wm + mt * 16 + (lane >> 2);
            if (cbase + 1 < VOCAB) {
                float2 v0 = make_float2(acc[mt][nt][0] + bv.x, acc[mt][nt][1] + bv.y);
                float2 v1 = make_float2(acc[mt][nt][2] + bv.x, acc[mt][nt][3] + bv.y);
                *reinterpret_cast<float2*>(C + (size_t)r0 * VOCAB + cbase) = v0;
                *reinterpret_cast<float2*>(C + (size_t)(r0 + 8) * VOCAB + cbase) = v1;
            }
        }
    }
}

// ================= fused kernel =================
__global__ __launch_bounds__(FTH, 1) __cluster_dims__(CLUSTER, 1, 1)
void fused_kernel(const int* __restrict__ X, const float* __restrict__ H0,
                  const float* __restrict__ Wxz, const float* __restrict__ Whz, const float* __restrict__ bz,
                  const float* __restrict__ Wxr, const float* __restrict__ Whr, const float* __restrict__ br,
                  const float* __restrict__ Wxh, const float* __restrict__ Whh, const float* __restrict__ bh,
                  const float* __restrict__ bq, float* __restrict__ C, float* __restrict__ outF)
{
    if (blockIdx.x < NREC) {
        rnn_body(X, H0, Wxz, Whz, bz, Wxr, Whr, br, Wxh, Whh, bh, outF);
    } else {
        gemm_body((int)blockIdx.x - NREC, bq, C);
    }
}

// ================= launch =================
extern "C" void kernel_launch(void* const* d_in, const int* in_sizes, int n_in,
                              void* d_out, int out_size) {
    const int*   X   = (const int*)  d_in[0];
    const float* H0  = (const float*)d_in[1];
    const float* Wxz = (const float*)d_in[2];
    const float* Whz = (const float*)d_in[3];
    const float* bz  = (const float*)d_in[4];
    const float* Wxr = (const float*)d_in[5];
    const float* Whr = (const float*)d_in[6];
    const float* br  = (const float*)d_in[7];
    const float* Wxh = (const float*)d_in[8];
    const float* Whh = (const float*)d_in[9];
    const float* bh  = (const float*)d_in[10];
    const float* Whq = (const float*)d_in[11];
    const float* bq  = (const float*)d_in[12];

    float* out  = (float*)d_out;
    float* outF = out + (out_size - BATCH * HID);

    static bool attr_set = false;
    if (!attr_set) {
        cudaFuncSetAttribute(fused_kernel, cudaFuncAttributeMaxDynamicSharedMemorySize,
                             (int)sizeof(RSmem));
        attr_set = true;
    }

    prog_reset_kernel<<<1, 64>>>();
    convB_kernel<<<(HID * VOCAB + 255) / 256, 256>>>(Whq);
    fused_kernel<<<NREC + NTM * NTN, FTH, sizeof(RSmem)>>>(
        X, H0, Wxz, Whz, bz, Wxr, Whr, br, Wxh, Whh, bh, bq, out, outF);
}

// round 12
// speedup vs baseline: 1.1573x; 1.1573x over previous
#include <cuda_runtime.h>
#include <cuda_bf16.h>
#include <cstdint>

#define BATCH 32
#define HID   256
#define VOCAB 10000
#define STEPS 256

// ---------------- config ----------------
#define CLUSTER 4
#define BPC     2
#define DPC     64
#define NREC    64                 // recurrence CTAs (bids 0..63, wave 1)
#define FTH     256                // threads per CTA (fused kernel)

#define GBM 128
#define GBN 128
#define GBK 16
#define GNC (HID / GBK)
#define NTN ((VOCAB + GBN - 1) / GBN)   // 79 N tiles
#define NTM ((STEPS * BATCH) / GBM)     // 64 M tiles

// ---------------- scratch (device globals: allocation-free) ----------------
__device__ __nv_bfloat16 g_Ahi[STEPS * BATCH * HID];
__device__ __nv_bfloat16 g_Alo[STEPS * BATCH * HID];
__device__ __nv_bfloat16 g_Bhi[HID * VOCAB];
__device__ __nv_bfloat16 g_Blo[HID * VOCAB];
__device__ unsigned g_prog[NREC];   // per-recurrence-CTA step progress (t+1)

__global__ void prog_reset_kernel() {
    if (threadIdx.x < NREC) g_prog[threadIdx.x] = 0u;
}

__global__ void convB_kernel(const float* __restrict__ W) {
    int i = blockIdx.x * 256 + threadIdx.x;
    if (i < HID * VOCAB) {
        float v = W[i];
        __nv_bfloat16 h = __float2bfloat16(v);
        g_Bhi[i] = h;
        g_Blo[i] = __float2bfloat16(v - __bfloat162float(h));
    }
}

__device__ __forceinline__ uint32_t sptr(const void* p) {
    return (uint32_t)__cvta_generic_to_shared(p);
}
__device__ __forceinline__ unsigned ld_acq(const unsigned* p) {
    unsigned v;
    asm volatile("ld.acquire.gpu.global.u32 %0, [%1];" : "=r"(v) : "l"(p) : "memory");
    return v;
}
__device__ __forceinline__ void st_rel(unsigned* p, unsigned v) {
    asm volatile("st.release.gpu.global.u32 [%0], %1;" :: "l"(p), "r"(v) : "memory");
}

#define FMA2(acc, a, b) \
    asm("fma.rn.f32x2 %0, %1, %2, %0;" : "+l"(acc) : "l"(a), "l"(b))

__device__ __forceinline__ float2 unpack2(unsigned long long v) {
    float2 f;
    asm("mov.b64 {%0, %1}, %2;" : "=f"(f.x), "=f"(f.y) : "l"(v));
    return f;
}

__device__ __forceinline__ void st_cluster_f32(uint32_t laddr, int rank, float v) {
    uint32_t ra;
    asm("mapa.shared::cluster.u32 %0, %1, %2;" : "=r"(ra) : "r"(laddr), "r"(rank));
    asm volatile("st.shared::cluster.f32 [%0], %1;" :: "r"(ra), "f"(v) : "memory");
}

#define CLUSTER_SYNC() do { \
    asm volatile("barrier.cluster.arrive.aligned;" ::: "memory"); \
    asm volatile("barrier.cluster.wait.aligned;"   ::: "memory"); \
} while (0)

// ---------------- smem overlays (one dynamic buffer) ----------------
struct RSmem {                           // recurrence CTAs (R6-exact layout)
    float4 Wq[3][HID / 4][DPC];          // 196608 B
    float4 hq[BPC][HID / 4];
    float4 rhq[BPC][HID / 4];
};
struct GSmem {                           // GEMM CTAs (32 KB region of same buffer)
    __nv_bfloat16 Ah[2][GBM * GBK];
    __nv_bfloat16 Al[2][GBM * GBK];
    __nv_bfloat16 Bh[2][GBK * GBN];
    __nv_bfloat16 Bl[2][GBK * GBN];
};

extern __shared__ __align__(16) char dyn_smem[];

// ================= recurrence body (gate-split phase 1, all 256 threads) =================
__device__ void rnn_body(const int* __restrict__ X, const float* __restrict__ H0,
                         const float* __restrict__ Wxz, const float* __restrict__ Whz, const float* __restrict__ bz,
                         const float* __restrict__ Wxr, const float* __restrict__ Whr, const float* __restrict__ br,
                         const float* __restrict__ Wxh, const float* __restrict__ Whh, const float* __restrict__ bh,
                         float* __restrict__ outF)
{
    RSmem* s = reinterpret_cast<RSmem*>(dyn_smem);
    const int tid  = threadIdx.x;
    const bool zg  = tid < 128;          // z-group: phase1 z-gate + all of phase2
    const int wtid = tid & 127;          // (b, d) index within group
    const int rank = (int)(blockIdx.x & (CLUSTER - 1));
    const int cid  = (int)(blockIdx.x >> 2);
    const int dim0 = rank * DPC;
    const int b    = wtid & 1;
    const int d    = wtid >> 1;
    const int bg   = cid * BPC + b;
    const int dim  = dim0 + d;

    // one-time weight slice load (all 256 threads help)
    for (int i = tid; i < 3 * (HID / 4) * DPC; i += FTH) {
        int g  = i / ((HID / 4) * DPC);
        int r  = i % ((HID / 4) * DPC);
        int kq = r / DPC;
        int dd = r % DPC;
        const float* W = (g == 0) ? Whz : ((g == 1) ? Whr : Whh);
        float4 v;
        v.x = W[(kq * 4 + 0) * HID + dim0 + dd];
        v.y = W[(kq * 4 + 1) * HID + dim0 + dd];
        v.z = W[(kq * 4 + 2) * HID + dim0 + dd];
        v.w = W[(kq * 4 + 3) * HID + dim0 + dd];
        s->Wq[g][kq][dd] = v;
    }
    if (tid < BPC * (HID / 4)) {
        int bb = tid >> 6;
        int kq = tid & 63;
        s->hq[bb][kq] = *reinterpret_cast<const float4*>(&H0[(cid * BPC + bb) * HID + kq * 4]);
    }
    // per-group biases
    const float bgate = zg ? bz[dim] : br[dim];   // z-group: b_z ; r-group: b_r
    const float bhv   = zg ? bh[dim] : 0.f;
    __syncthreads();
    CLUSTER_SYNC();

    const uint32_t rh_addr = sptr(&reinterpret_cast<float*>(s->rhq)[b * HID + dim]);
    const uint32_t h_addr  = sptr(&reinterpret_cast<float*>(s->hq)[b * HID + dim]);
    const ulonglong2* wgate = reinterpret_cast<const ulonglong2*>(&s->Wq[zg ? 0 : 1][0][d]);
    const ulonglong2* whh   = reinterpret_cast<const ulonglong2*>(&s->Wq[2][0][d]);

    #pragma unroll 1
    for (int t = 0; t < STEPS; ++t) {
        float zv = 0.f, hold = 0.f, xh = 0.f;   // carried in z-group registers across sync

        // ---- phase 1: each group computes ONE gate dot ----
        {
            int   xv = X[bg * STEPS + t];
            float xg = zg ? Wxz[xv * HID + dim] : Wxr[xv * HID + dim];
            hold = reinterpret_cast<const float*>(s->hq)[b * HID + dim];
            if (zg) xh = Wxh[xv * HID + dim];    // prefetch; LDG overlaps the dot

            unsigned long long a0 = 0ull, a1 = 0ull;
            const ulonglong2* hp = reinterpret_cast<const ulonglong2*>(&s->hq[b][0]);
            #pragma unroll 16
            for (int kq = 0; kq < HID / 4; ++kq) {
                ulonglong2 h2 = hp[kq];
                ulonglong2 a  = wgate[kq * DPC];
                FMA2(a0, a.x, h2.x); FMA2(a1, a.y, h2.y);
            }
            float2 p0 = unpack2(a0), p1 = unpack2(a1);
            float gate = 1.f / (1.f + expf(-(((p0.x + p0.y) + (p1.x + p1.y)) + xg + bgate)));
            if (zg) {
                zv = gate;
            } else {
                float rh = gate * hold;
                #pragma unroll
                for (int rr = 0; rr < CLUSTER; ++rr) st_cluster_f32(rh_addr, rr, rh);
            }
        }
        CLUSTER_SYNC();

        // ---- phase 2: z-group computes h_tilda + h update ----
        if (zg) {
            unsigned long long ah0 = 0ull, ah1 = 0ull;
            const ulonglong2* rp = reinterpret_cast<const ulonglong2*>(&s->rhq[b][0]);
            #pragma unroll 16
            for (int kq = 0; kq < HID / 4; ++kq) {
                ulonglong2 r2 = rp[kq];
                ulonglong2 a  = whh[kq * DPC];
                FMA2(ah0, a.x, r2.x); FMA2(ah1, a.y, r2.y);
            }
            float2 h0 = unpack2(ah0), h1 = unpack2(ah1);
            float htl  = tanhf(((h0.x + h0.y) + (h1.x + h1.y)) + xh + bhv);
            float hnew = zv * hold + (1.f - zv) * htl;
            #pragma unroll
            for (int rr = 0; rr < CLUSTER; ++rr) st_cluster_f32(h_addr, rr, hnew);

            int row = t * BATCH + bg;
            __nv_bfloat16 hb = __float2bfloat16(hnew);
            g_Ahi[row * HID + dim] = hb;
            g_Alo[row * HID + dim] = __float2bfloat16(hnew - __bfloat162float(hb));
            if (t == STEPS - 1) outF[bg * HID + dim] = hnew;
        }
        CLUSTER_SYNC();
        if (tid == 0) st_rel(&g_prog[blockIdx.x], (unsigned)(t + 1));
    }
}

// ================= GEMM body (round-3 logic, smem from dynamic buffer) =================
#define CP16(dst, src, sz) \
    asm volatile("cp.async.cg.shared.global [%0], [%1], 16, %2;" :: "r"(dst), "l"(src), "r"(sz))
#define LDSM4(r, addr) \
    asm volatile("ldmatrix.sync.aligned.m8n8.x4.shared.b16 {%0,%1,%2,%3}, [%4];" \
        : "=r"((r)[0]), "=r"((r)[1]), "=r"((r)[2]), "=r"((r)[3]) : "r"(addr))
#define LDSMT2(r, addr) \
    asm volatile("ldmatrix.sync.aligned.m8n8.x2.trans.shared.b16 {%0,%1}, [%2];" \
        : "=r"((r)[0]), "=r"((r)[1]) : "r"(addr))
#define MMA16816(d, a, b) \
    asm volatile("mma.sync.aligned.m16n8k16.row.col.f32.bf16.bf16.f32 " \
        "{%0,%1,%2,%3}, {%4,%5,%6,%7}, {%8,%9}, {%0,%1,%2,%3};" \
        : "+f"((d)[0]), "+f"((d)[1]), "+f"((d)[2]), "+f"((d)[3]) \
        : "r"((a)[0]), "r"((a)[1]), "r"((a)[2]), "r"((a)[3]), "r"((b)[0]), "r"((b)[1]))

__device__ void gemm_body(int g, const float* __restrict__ bias, float* __restrict__ C)
{
    GSmem* gs = reinterpret_cast<GSmem*>(dyn_smem);
    const int tid  = threadIdx.x;
    const int lane = tid & 31;
    const int warp = tid >> 5;
    const int wm   = (warp >> 2) * 64;
    const int wn   = (warp & 3) * 32;
    const int mtile = g / NTN;
    const int ntile = g % NTN;
    const int m0   = mtile * GBM;
    const int n0   = ntile * GBN;

    // ---- band wait: all 64 recurrence CTAs past step 4*mtile+3 ----
    const unsigned need = (unsigned)(mtile * 4 + 4);
    if (tid < NREC) {
        while (ld_acq(&g_prog[tid]) < need) __nanosleep(256);
    }
    __syncthreads();

    float acc[4][4][4];
    #pragma unroll
    for (int i = 0; i < 4; ++i)
        #pragma unroll
        for (int j = 0; j < 4; ++j)
            #pragma unroll
            for (int q = 0; q < 4; ++q) acc[i][j][q] = 0.f;

    auto load_stage = [&](int st, int k0) {
        #pragma unroll
        for (int i = 0; i < 2; ++i) {
            int idx = tid + (i << 8);
            int sel = idx >> 8;
            int r   = idx & 255;
            int m   = r >> 1;
            int ku  = r & 1;
            const __nv_bfloat16* gp = (sel ? g_Alo : g_Ahi) + (size_t)(m0 + m) * HID + k0 + ku * 8;
            uint32_t dd = sptr(sel ? gs->Al[st] : gs->Ah[st]) + m * 32 + ((ku ^ ((m >> 2) & 1)) << 4);
            CP16(dd, gp, 16);
        }
        #pragma unroll
        for (int i = 0; i < 2; ++i) {
            int idx = tid + (i << 8);
            int sel = idx >> 8;
            int r   = idx & 255;
            int k   = r >> 4;
            int nu  = r & 15;
            int col = n0 + nu * 8;
            const __nv_bfloat16* gp = (sel ? g_Blo : g_Bhi) + (size_t)(k0 + k) * VOCAB + col;
            uint32_t dd = sptr(sel ? gs->Bl[st] : gs->Bh[st]) + k * 256 + ((nu ^ (k & 7)) << 4);
            int sz = (col + 8 <= VOCAB) ? 16 : 0;
            CP16(dd, gp, sz);
        }
    };

    load_stage(0, 0);
    asm volatile("cp.async.commit_group;");

    const int lrow = lane & 15;
    const int lkb  = (lane >> 4) & 1;

    #pragma unroll 1
    for (int c = 0; c < GNC; ++c) {
        if (c + 1 < GNC) load_stage((c + 1) & 1, (c + 1) * GBK);
        asm volatile("cp.async.commit_group;");
        asm volatile("cp.async.wait_group 1;");
        __syncthreads();

        const int st = c & 1;
        uint32_t ah[4][4], al[4][4], bh[4][2], bl[4][2];
        #pragma unroll
        for (int mt = 0; mt < 4; ++mt) {
            int m = wm + mt * 16 + lrow;
            uint32_t off = m * 32 + ((lkb ^ ((m >> 2) & 1)) << 4);
            LDSM4(ah[mt], sptr(gs->Ah[st]) + off);
            LDSM4(al[mt], sptr(gs->Al[st]) + off);
        }
        #pragma unroll
        for (int nt = 0; nt < 4; ++nt) {
            int k = lrow;
            int n = wn + nt * 8;
            uint32_t off = k * 256 + (((n >> 3) ^ (k & 7)) << 4);
            LDSMT2(bh[nt], sptr(gs->Bh[st]) + off);
            LDSMT2(bl[nt], sptr(gs->Bl[st]) + off);
        }
        #pragma unroll
        for (int mt = 0; mt < 4; ++mt)
            #pragma unroll
            for (int nt = 0; nt < 4; ++nt) {
                MMA16816(acc[mt][nt], ah[mt], bh[nt]);
                MMA16816(acc[mt][nt], ah[mt], bl[nt]);
                MMA16816(acc[mt][nt], al[mt], bh[nt]);
            }
        __syncthreads();
    }

    #pragma unroll
    for (int nt = 0; nt < 4; ++nt) {
        int cbase = n0 + wn + nt * 8 + 2 * (lane & 3);
        float2 bv = make_float2(0.f, 0.f);
        if (cbase + 1 < VOCAB) bv = *reinterpret_cast<const float2*>(bias + cbase);
        #pragma unroll
        for (int mt = 0; mt < 4; ++mt) {
            int r0 = m0 + wm + mt * 16 + (lane >> 2);
            if (cbase + 1 < VOCAB) {
                float2 v0 = make_float2(acc[mt][nt][0] + bv.x, acc[mt][nt][1] + bv.y);
                float2 v1 = make_float2(acc[mt][nt][2] + bv.x, acc[mt][nt][3] + bv.y);
                *reinterpret_cast<float2*>(C + (size_t)r0 * VOCAB + cbase) = v0;
                *reinterpret_cast<float2*>(C + (size_t)(r0 + 8) * VOCAB + cbase) = v1;
            }
        }
    }
}

// ================= fused kernel =================
__global__ __launch_bounds__(FTH, 1) __cluster_dims__(CLUSTER, 1, 1)
void fused_kernel(const int* __restrict__ X, const float* __restrict__ H0,
                  const float* __restrict__ Wxz, const float* __restrict__ Whz, const float* __restrict__ bz,
                  const float* __restrict__ Wxr, const float* __restrict__ Whr, const float* __restrict__ br,
                  const float* __restrict__ Wxh, const float* __restrict__ Whh, const float* __restrict__ bh,
                  const float* __restrict__ bq, float* __restrict__ C, float* __restrict__ outF)
{
    if (blockIdx.x < NREC) {
        rnn_body(X, H0, Wxz, Whz, bz, Wxr, Whr, br, Wxh, Whh, bh, outF);
    } else {
        gemm_body((int)blockIdx.x - NREC, bq, C);
    }
}

// ================= launch =================
extern "C" void kernel_launch(void* const* d_in, const int* in_sizes, int n_in,
                              void* d_out, int out_size) {
    const int*   X   = (const int*)  d_in[0];
    const float* H0  = (const float*)d_in[1];
    const float* Wxz = (const float*)d_in[2];
    const float* Whz = (const float*)d_in[3];
    const float* bz  = (const float*)d_in[4];
    const float* Wxr = (const float*)d_in[5];
    const float* Whr = (const float*)d_in[6];
    const float* br  = (const float*)d_in[7];
    const float* Wxh = (const float*)d_in[8];
    const float* Whh = (const float*)d_in[9];
    const float* bh  = (const float*)d_in[10];
    const float* Whq = (const float*)d_in[11];
    const float* bq  = (const float*)d_in[12];

    float* out  = (float*)d_out;
    float* outF = out + (out_size - BATCH * HID);

    static bool attr_set = false;
    if (!attr_set) {
        cudaFuncSetAttribute(fused_kernel, cudaFuncAttributeMaxDynamicSharedMemorySize,
                             (int)sizeof(RSmem));
        attr_set = true;
    }

    prog_reset_kernel<<<1, 64>>>();
    convB_kernel<<<(HID * VOCAB + 255) / 256, 256>>>(Whq);
    fused_kernel<<<NREC + NTM * NTN, FTH, sizeof(RSmem)>>>(
        X, H0, Wxz, Whz, bz, Wxr, Whr, br, Wxh, Whh, bh, bq, out, outF);
}

// round 13
// speedup vs baseline: 1.3162x; 1.1374x over previous
#include <cuda_runtime.h>
#include <cuda_bf16.h>
#include <cstdint>

#define BATCH 32
#define HID   256
#define VOCAB 10000
#define STEPS 256

// ---------------- config ----------------
#define CLUSTER 4
#define BPC     2
#define DPC     64
#define NREC    64                 // recurrence CTAs (bids 0..63, wave 1)
#define FTH     256                // threads per CTA (fused kernel)

#define GBM 128
#define GBN 128
#define GBK 16
#define GNC (HID / GBK)
#define NTN ((VOCAB + GBN - 1) / GBN)   // 79 N tiles
#define NTM ((STEPS * BATCH) / GBM)     // 64 M tiles

// ---------------- scratch (device globals: allocation-free) ----------------
__device__ __nv_bfloat16 g_Ahi[STEPS * BATCH * HID];
__device__ __nv_bfloat16 g_Alo[STEPS * BATCH * HID];
__device__ __nv_bfloat16 g_Bhi[HID * VOCAB];
__device__ __nv_bfloat16 g_Blo[HID * VOCAB];
__device__ unsigned g_prog[NREC];   // per-recurrence-CTA step progress (t+1)

__global__ void prog_reset_kernel() {
    if (threadIdx.x < NREC) g_prog[threadIdx.x] = 0u;
}

__global__ void convB_kernel(const float* __restrict__ W) {
    int i = blockIdx.x * 256 + threadIdx.x;
    if (i < HID * VOCAB) {
        float v = W[i];
        __nv_bfloat16 h = __float2bfloat16(v);
        g_Bhi[i] = h;
        g_Blo[i] = __float2bfloat16(v - __bfloat162float(h));
    }
}

__device__ __forceinline__ uint32_t sptr(const void* p) {
    return (uint32_t)__cvta_generic_to_shared(p);
}
__device__ __forceinline__ unsigned ld_acq(const unsigned* p) {
    unsigned v;
    asm volatile("ld.acquire.gpu.global.u32 %0, [%1];" : "=r"(v) : "l"(p) : "memory");
    return v;
}
__device__ __forceinline__ void st_rel(unsigned* p, unsigned v) {
    asm volatile("st.release.gpu.global.u32 [%0], %1;" :: "l"(p), "r"(v) : "memory");
}

#define FMA2(acc, a, b) \
    asm("fma.rn.f32x2 %0, %1, %2, %0;" : "+l"(acc) : "l"(a), "l"(b))

__device__ __forceinline__ float2 unpack2(unsigned long long v) {
    float2 f;
    asm("mov.b64 {%0, %1}, %2;" : "=f"(f.x), "=f"(f.y) : "l"(v));
    return f;
}

__device__ __forceinline__ void st_cluster_f32(uint32_t laddr, int rank, float v) {
    uint32_t ra;
    asm("mapa.shared::cluster.u32 %0, %1, %2;" : "=r"(ra) : "r"(laddr), "r"(rank));
    asm volatile("st.shared::cluster.f32 [%0], %1;" :: "r"(ra), "f"(v) : "memory");
}

#define CLUSTER_SYNC() do { \
    asm volatile("barrier.cluster.arrive.aligned;" ::: "memory"); \
    asm volatile("barrier.cluster.wait.aligned;"   ::: "memory"); \
} while (0)

// ---------------- smem overlays (one dynamic buffer) ----------------
struct RSmem {                           // recurrence CTAs
    float4 Wq[3][HID / 4][DPC];          // 196608 B
    float4 hq[BPC][HID / 4];
    float4 rhq[BPC][HID / 4];
    int    xs[BPC][STEPS];               // preloaded tokens (survive L1 flush)
};
struct GSmem {                           // GEMM CTAs (32 KB region of same buffer)
    __nv_bfloat16 Ah[2][GBM * GBK];
    __nv_bfloat16 Al[2][GBM * GBK];
    __nv_bfloat16 Bh[2][GBK * GBN];
    __nv_bfloat16 Bl[2][GBK * GBN];
};

extern __shared__ __align__(16) char dyn_smem[];

// ================= recurrence body (R10-exact + gather prefetch) =================
__device__ void rnn_body(const int* __restrict__ X, const float* __restrict__ H0,
                         const float* __restrict__ Wxz, const float* __restrict__ Whz, const float* __restrict__ bz,
                         const float* __restrict__ Wxr, const float* __restrict__ Whr, const float* __restrict__ br,
                         const float* __restrict__ Wxh, const float* __restrict__ Whh, const float* __restrict__ bh,
                         float* __restrict__ outF)
{
    RSmem* s = reinterpret_cast<RSmem*>(dyn_smem);
    const int tid    = threadIdx.x;
    const bool active = tid < 128;
    const int rank = (int)(blockIdx.x & (CLUSTER - 1));
    const int cid  = (int)(blockIdx.x >> 2);
    const int dim0 = rank * DPC;
    const int b    = tid & 1;
    const int d    = active ? (tid >> 1) : 0;
    const int bg   = cid * BPC + b;
    const int dim  = dim0 + d;

    // one-time weight slice load (all 256 threads help)
    for (int i = tid; i < 3 * (HID / 4) * DPC; i += FTH) {
        int g  = i / ((HID / 4) * DPC);
        int r  = i % ((HID / 4) * DPC);
        int kq = r / DPC;
        int dd = r % DPC;
        const float* W = (g == 0) ? Whz : ((g == 1) ? Whr : Whh);
        float4 v;
        v.x = W[(kq * 4 + 0) * HID + dim0 + dd];
        v.y = W[(kq * 4 + 1) * HID + dim0 + dd];
        v.z = W[(kq * 4 + 2) * HID + dim0 + dd];
        v.w = W[(kq * 4 + 3) * HID + dim0 + dd];
        s->Wq[g][kq][dd] = v;
    }
    if (tid < BPC * (HID / 4)) {
        int bb = tid >> 6;
        int kq = tid & 63;
        s->hq[bb][kq] = *reinterpret_cast<const float4*>(&H0[(cid * BPC + bb) * HID + kq * 4]);
    }
    // one-time token preload (removes per-step flushed-L1 LDG of X)
    for (int i = tid; i < BPC * STEPS; i += FTH) {
        int bb = i / STEPS;
        int tt = i % STEPS;
        s->xs[bb][tt] = X[(cid * BPC + bb) * STEPS + tt];
    }
    const float bzv = bz[dim];
    const float brv = br[dim];
    const float bhv = bh[dim];
    __syncthreads();
    CLUSTER_SYNC();   // weights + h0 + xs visible cluster-wide (once, off hot loop)

    const uint32_t rh_addr = sptr(&reinterpret_cast<float*>(s->rhq)[b * HID + dim]);
    const uint32_t h_addr  = sptr(&reinterpret_cast<float*>(s->hq)[b * HID + dim]);

    // initial gather prefetch for t=0 (values live in registers, flush-immune)
    float pxz = 0.f, pxr = 0.f, pxh = 0.f;
    if (active) {
        int xv0 = s->xs[b][0];
        pxz = Wxz[xv0 * HID + dim];
        pxr = Wxr[xv0 * HID + dim];
        pxh = Wxh[xv0 * HID + dim];
    }

    #pragma unroll 1
    for (int t = 0; t < STEPS; ++t) {
        float zv = 0.f, hold = 0.f, xh = 0.f;   // carried in registers across sync

        if (active) {
            float xz = pxz;
            float xr = pxr;
            xh = pxh;

            // prefetch next step's gathers; LDG latency hides behind dot+syncs+phase2
            int tn  = (t + 1 < STEPS) ? (t + 1) : t;
            int xvn = s->xs[b][tn];
            pxz = Wxz[xvn * HID + dim];
            pxr = Wxr[xvn * HID + dim];
            pxh = Wxh[xvn * HID + dim];

            hold = reinterpret_cast<const float*>(s->hq)[b * HID + dim];

            unsigned long long az0 = 0ull, az1 = 0ull, ar0 = 0ull, ar1 = 0ull;
            const ulonglong2* wz = reinterpret_cast<const ulonglong2*>(&s->Wq[0][0][d]);
            const ulonglong2* wr = reinterpret_cast<const ulonglong2*>(&s->Wq[1][0][d]);
            const ulonglong2* hp = reinterpret_cast<const ulonglong2*>(&s->hq[b][0]);
            #pragma unroll 16
            for (int kq = 0; kq < HID / 4; ++kq) {
                ulonglong2 h2 = hp[kq];
                ulonglong2 a  = wz[kq * DPC];
                ulonglong2 c  = wr[kq * DPC];
                FMA2(az0, a.x, h2.x); FMA2(az1, a.y, h2.y);
                FMA2(ar0, c.x, h2.x); FMA2(ar1, c.y, h2.y);
            }
            float2 z0 = unpack2(az0), z1 = unpack2(az1);
            float2 r0 = unpack2(ar0), r1 = unpack2(ar1);
            zv = 1.f / (1.f + expf(-(((z0.x + z0.y) + (z1.x + z1.y)) + xz + bzv)));
            float rv = 1.f / (1.f + expf(-(((r0.x + r0.y) + (r1.x + r1.y)) + xr + brv)));
            float rh = rv * hold;
            #pragma unroll
            for (int rr = 0; rr < CLUSTER; ++rr) st_cluster_f32(rh_addr, rr, rh);
        }
        CLUSTER_SYNC();

        if (active) {
            unsigned long long ah0 = 0ull, ah1 = 0ull;
            const ulonglong2* wh = reinterpret_cast<const ulonglong2*>(&s->Wq[2][0][d]);
            const ulonglong2* rp = reinterpret_cast<const ulonglong2*>(&s->rhq[b][0]);
            #pragma unroll 16
            for (int kq = 0; kq < HID / 4; ++kq) {
                ulonglong2 r2 = rp[kq];
                ulonglong2 a  = wh[kq * DPC];
                FMA2(ah0, a.x, r2.x); FMA2(ah1, a.y, r2.y);
            }
            float2 h0 = unpack2(ah0), h1 = unpack2(ah1);
            float htl  = tanhf(((h0.x + h0.y) + (h1.x + h1.y)) + xh + bhv);
            float hnew = zv * hold + (1.f - zv) * htl;
            #pragma unroll
            for (int rr = 0; rr < CLUSTER; ++rr) st_cluster_f32(h_addr, rr, hnew);

            int row = t * BATCH + bg;
            __nv_bfloat16 hb = __float2bfloat16(hnew);
            g_Ahi[row * HID + dim] = hb;
            g_Alo[row * HID + dim] = __float2bfloat16(hnew - __bfloat162float(hb));
            if (t == STEPS - 1) outF[bg * HID + dim] = hnew;
        }
        CLUSTER_SYNC();
        if (tid == 0) st_rel(&g_prog[blockIdx.x], (unsigned)(t + 1));
    }
}

// ================= GEMM body (round-3 logic, smem from dynamic buffer) =================
#define CP16(dst, src, sz) \
    asm volatile("cp.async.cg.shared.global [%0], [%1], 16, %2;" :: "r"(dst), "l"(src), "r"(sz))
#define LDSM4(r, addr) \
    asm volatile("ldmatrix.sync.aligned.m8n8.x4.shared.b16 {%0,%1,%2,%3}, [%4];" \
        : "=r"((r)[0]), "=r"((r)[1]), "=r"((r)[2]), "=r"((r)[3]) : "r"(addr))
#define LDSMT2(r, addr) \
    asm volatile("ldmatrix.sync.aligned.m8n8.x2.trans.shared.b16 {%0,%1}, [%2];" \
        : "=r"((r)[0]), "=r"((r)[1]) : "r"(addr))
#define MMA16816(d, a, b) \
    asm volatile("mma.sync.aligned.m16n8k16.row.col.f32.bf16.bf16.f32 " \
        "{%0,%1,%2,%3}, {%4,%5,%6,%7}, {%8,%9}, {%0,%1,%2,%3};" \
        : "+f"((d)[0]), "+f"((d)[1]), "+f"((d)[2]), "+f"((d)[3]) \
        : "r"((a)[0]), "r"((a)[1]), "r"((a)[2]), "r"((a)[3]), "r"((b)[0]), "r"((b)[1]))

__device__ void gemm_body(int g, const float* __restrict__ bias, float* __restrict__ C)
{
    GSmem* gs = reinterpret_cast<GSmem*>(dyn_smem);
    const int tid  = threadIdx.x;
    const int lane = tid & 31;
    const int warp = tid >> 5;
    const int wm   = (warp >> 2) * 64;
    const int wn   = (warp & 3) * 32;
    const int mtile = g / NTN;
    const int ntile = g % NTN;
    const int m0   = mtile * GBM;
    const int n0   = ntile * GBN;

    // ---- band wait: all 64 recurrence CTAs past step 4*mtile+3 ----
    const unsigned need = (unsigned)(mtile * 4 + 4);
    if (tid < NREC) {
        while (ld_acq(&g_prog[tid]) < need) __nanosleep(256);
    }
    __syncthreads();

    float acc[4][4][4];
    #pragma unroll
    for (int i = 0; i < 4; ++i)
        #pragma unroll
        for (int j = 0; j < 4; ++j)
            #pragma unroll
            for (int q = 0; q < 4; ++q) acc[i][j][q] = 0.f;

    auto load_stage = [&](int st, int k0) {
        #pragma unroll
        for (int i = 0; i < 2; ++i) {
            int idx = tid + (i << 8);
            int sel = idx >> 8;
            int r   = idx & 255;
            int m   = r >> 1;
            int ku  = r & 1;
            const __nv_bfloat16* gp = (sel ? g_Alo : g_Ahi) + (size_t)(m0 + m) * HID + k0 + ku * 8;
            uint32_t dd = sptr(sel ? gs->Al[st] : gs->Ah[st]) + m * 32 + ((ku ^ ((m >> 2) & 1)) << 4);
            CP16(dd, gp, 16);
        }
        #pragma unroll
        for (int i = 0; i < 2; ++i) {
            int idx = tid + (i << 8);
            int sel = idx >> 8;
            int r   = idx & 255;
            int k   = r >> 4;
            int nu  = r & 15;
            int col = n0 + nu * 8;
            const __nv_bfloat16* gp = (sel ? g_Blo : g_Bhi) + (size_t)(k0 + k) * VOCAB + col;
            uint32_t dd = sptr(sel ? gs->Bl[st] : gs->Bh[st]) + k * 256 + ((nu ^ (k & 7)) << 4);
            int sz = (col + 8 <= VOCAB) ? 16 : 0;
            CP16(dd, gp, sz);
        }
    };

    load_stage(0, 0);
    asm volatile("cp.async.commit_group;");

    const int lrow = lane & 15;
    const int lkb  = (lane >> 4) & 1;

    #pragma unroll 1
    for (int c = 0; c < GNC; ++c) {
        if (c + 1 < GNC) load_stage((c + 1) & 1, (c + 1) * GBK);
        asm volatile("cp.async.commit_group;");
        asm volatile("cp.async.wait_group 1;");
        __syncthreads();

        const int st = c & 1;
        uint32_t ah[4][4], al[4][4], bh[4][2], bl[4][2];
        #pragma unroll
        for (int mt = 0; mt < 4; ++mt) {
            int m = wm + mt * 16 + lrow;
            uint32_t off = m * 32 + ((lkb ^ ((m >> 2) & 1)) << 4);
            LDSM4(ah[mt], sptr(gs->Ah[st]) + off);
            LDSM4(al[mt], sptr(gs->Al[st]) + off);
        }
        #pragma unroll
        for (int nt = 0; nt < 4; ++nt) {
            int k = lrow;
            int n = wn + nt * 8;
            uint32_t off = k * 256 + (((n >> 3) ^ (k & 7)) << 4);
            LDSMT2(bh[nt], sptr(gs->Bh[st]) + off);
            LDSMT2(bl[nt], sptr(gs->Bl[st]) + off);
        }
        #pragma unroll
        for (int mt = 0; mt < 4; ++mt)
            #pragma unroll
            for (int nt = 0; nt < 4; ++nt) {
                MMA16816(acc[mt][nt], ah[mt], bh[nt]);
                MMA16816(acc[mt][nt], ah[mt], bl[nt]);
                MMA16816(acc[mt][nt], al[mt], bh[nt]);
            }
        __syncthreads();
    }

    #pragma unroll
    for (int nt = 0; nt < 4; ++nt) {
        int cbase = n0 + wn + nt * 8 + 2 * (lane & 3);
        float2 bv = make_float2(0.f, 0.f);
        if (cbase + 1 < VOCAB) bv = *reinterpret_cast<const float2*>(bias + cbase);
        #pragma unroll
        for (int mt = 0; mt < 4; ++mt) {
            int r0 = m0 + wm + mt * 16 + (lane >> 2);
            if (cbase + 1 < VOCAB) {
                float2 v0 = make_float2(acc[mt][nt][0] + bv.x, acc[mt][nt][1] + bv.y);
                float2 v1 = make_float2(acc[mt][nt][2] + bv.x, acc[mt][nt][3] + bv.y);
                *reinterpret_cast<float2*>(C + (size_t)r0 * VOCAB + cbase) = v0;
                *reinterpret_cast<float2*>(C + (size_t)(r0 + 8) * VOCAB + cbase) = v1;
            }
        }
    }
}

// ================= fused kernel =================
__global__ __launch_bounds__(FTH, 1) __cluster_dims__(CLUSTER, 1, 1)
void fused_kernel(const int* __restrict__ X, const float* __restrict__ H0,
                  const float* __restrict__ Wxz, const float* __restrict__ Whz, const float* __restrict__ bz,
                  const float* __restrict__ Wxr, const float* __restrict__ Whr, const float* __restrict__ br,
                  const float* __restrict__ Wxh, const float* __restrict__ Whh, const float* __restrict__ bh,
                  const float* __restrict__ bq, float* __restrict__ C, float* __restrict__ outF)
{
    if (blockIdx.x < NREC) {
        rnn_body(X, H0, Wxz, Whz, bz, Wxr, Whr, br, Wxh, Whh, bh, outF);
    } else {
        gemm_body((int)blockIdx.x - NREC, bq, C);
    }
}

// ================= launch =================
extern "C" void kernel_launch(void* const* d_in, const int* in_sizes, int n_in,
                              void* d_out, int out_size) {
    const int*   X   = (const int*)  d_in[0];
    const float* H0  = (const float*)d_in[1];
    const float* Wxz = (const float*)d_in[2];
    const float* Whz = (const float*)d_in[3];
    const float* bz  = (const float*)d_in[4];
    const float* Wxr = (const float*)d_in[5];
    const float* Whr = (const float*)d_in[6];
    const float* br  = (const float*)d_in[7];
    const float* Wxh = (const float*)d_in[8];
    const float* Whh = (const float*)d_in[9];
    const float* bh  = (const float*)d_in[10];
    const float* Whq = (const float*)d_in[11];
    const float* bq  = (const float*)d_in[12];

    float* out  = (float*)d_out;
    float* outF = out + (out_size - BATCH * HID);

    static bool attr_set = false;
    if (!attr_set) {
        cudaFuncSetAttribute(fused_kernel, cudaFuncAttributeMaxDynamicSharedMemorySize,
                             (int)sizeof(RSmem));
        attr_set = true;
    }

    prog_reset_kernel<<<1, 64>>>();
    convB_kernel<<<(HID * VOCAB + 255) / 256, 256>>>(Whq);
    fused_kernel<<<NREC + NTM * NTN, FTH, sizeof(RSmem)>>>(
        X, H0, Wxz, Whz, bz, Wxr, Whr, br, Wxh, Whh, bh, bq, out, outF);
}

// round 14
// speedup vs baseline: 1.3327x; 1.0125x over previous
#include <cuda_runtime.h>
#include <cuda_bf16.h>
#include <cstdint>

#define BATCH 32
#define HID   256
#define VOCAB 10000
#define STEPS 256

// ---------------- config ----------------
#define CLUSTER 4
#define BPC     2
#define DPC     64
#define NREC    64                 // recurrence CTAs (bids 0..63, wave 1)
#define FTH     256                // threads per CTA (fused kernel)

#define GBM 128
#define GBN 128
#define GBK 16
#define GNC (HID / GBK)
#define NTN ((VOCAB + GBN - 1) / GBN)   // 79 N tiles
#define NTM ((STEPS * BATCH) / GBM)     // 64 M tiles

// ---------------- scratch (device globals: allocation-free) ----------------
__device__ __nv_bfloat16 g_Ahi[STEPS * BATCH * HID];
__device__ __nv_bfloat16 g_Alo[STEPS * BATCH * HID];
__device__ __nv_bfloat16 g_Bhi[HID * VOCAB];
__device__ __nv_bfloat16 g_Blo[HID * VOCAB];
__device__ unsigned g_prog[NREC];   // per-recurrence-CTA step progress (t+1)

__global__ void prog_reset_kernel() {
    if (threadIdx.x < NREC) g_prog[threadIdx.x] = 0u;
}

__global__ void convB_kernel(const float* __restrict__ W) {
    int i = blockIdx.x * 256 + threadIdx.x;
    if (i < HID * VOCAB) {
        float v = W[i];
        __nv_bfloat16 h = __float2bfloat16(v);
        g_Bhi[i] = h;
        g_Blo[i] = __float2bfloat16(v - __bfloat162float(h));
    }
}

__device__ __forceinline__ uint32_t sptr(const void* p) {
    return (uint32_t)__cvta_generic_to_shared(p);
}
__device__ __forceinline__ unsigned ld_acq(const unsigned* p) {
    unsigned v;
    asm volatile("ld.acquire.gpu.global.u32 %0, [%1];" : "=r"(v) : "l"(p) : "memory");
    return v;
}
__device__ __forceinline__ void st_rel(unsigned* p, unsigned v) {
    asm volatile("st.release.gpu.global.u32 [%0], %1;" :: "l"(p), "r"(v) : "memory");
}

#define FMA2(acc, a, b) \
    asm("fma.rn.f32x2 %0, %1, %2, %0;" : "+l"(acc) : "l"(a), "l"(b))

__device__ __forceinline__ float2 unpack2(unsigned long long v) {
    float2 f;
    asm("mov.b64 {%0, %1}, %2;" : "=f"(f.x), "=f"(f.y) : "l"(v));
    return f;
}

__device__ __forceinline__ uint32_t mapa_rank(uint32_t laddr, int rank) {
    uint32_t ra;
    asm("mapa.shared::cluster.u32 %0, %1, %2;" : "=r"(ra) : "r"(laddr), "r"(rank));
    return ra;
}
__device__ __forceinline__ void st_cluster_addr(uint32_t raddr, float v) {
    asm volatile("st.shared::cluster.f32 [%0], %1;" :: "r"(raddr), "f"(v) : "memory");
}

#define CLUSTER_ARRIVE() asm volatile("barrier.cluster.arrive.aligned;" ::: "memory")
#define CLUSTER_WAIT()   asm volatile("barrier.cluster.wait.aligned;"   ::: "memory")
#define CLUSTER_SYNC() do { CLUSTER_ARRIVE(); CLUSTER_WAIT(); } while (0)

// fast transcendentals: MUFU-based, rel err ~1e-6 (threshold 1e-3)
__device__ __forceinline__ float fast_sigmoid(float x) {
    float e = __expf(-x);
    return __fdividef(1.f, 1.f + e);
}
__device__ __forceinline__ float fast_tanh(float x) {
    float e = __expf(-2.f * x);
    return __fdividef(2.f, 1.f + e) - 1.f;
}

// ---------------- smem overlays (one dynamic buffer) ----------------
struct RSmem {                           // recurrence CTAs
    float4 Wq[3][HID / 4][DPC];          // 196608 B
    float4 hq[BPC][HID / 4];
    float4 rhq[BPC][HID / 4];
    int    xs[BPC][STEPS];               // preloaded tokens (survive L1 flush)
};
struct GSmem {                           // GEMM CTAs (32 KB region of same buffer)
    __nv_bfloat16 Ah[2][GBM * GBK];
    __nv_bfloat16 Al[2][GBM * GBK];
    __nv_bfloat16 Bh[2][GBK * GBN];
    __nv_bfloat16 Bl[2][GBK * GBN];
};

extern __shared__ __align__(16) char dyn_smem[];

// ================= recurrence body (R13 + fast math + split-barrier prefetch) =================
__device__ void rnn_body(const int* __restrict__ X, const float* __restrict__ H0,
                         const float* __restrict__ Wxz, const float* __restrict__ Whz, const float* __restrict__ bz,
                         const float* __restrict__ Wxr, const float* __restrict__ Whr, const float* __restrict__ br,
                         const float* __restrict__ Wxh, const float* __restrict__ Whh, const float* __restrict__ bh,
                         float* __restrict__ outF)
{
    RSmem* s = reinterpret_cast<RSmem*>(dyn_smem);
    const int tid    = threadIdx.x;
    const bool active = tid < 128;
    const int rank = (int)(blockIdx.x & (CLUSTER - 1));
    const int cid  = (int)(blockIdx.x >> 2);
    const int dim0 = rank * DPC;
    const int b    = tid & 1;
    const int d    = active ? (tid >> 1) : 0;
    const int bg   = cid * BPC + b;
    const int dim  = dim0 + d;

    // one-time weight slice load (all 256 threads help)
    for (int i = tid; i < 3 * (HID / 4) * DPC; i += FTH) {
        int g  = i / ((HID / 4) * DPC);
        int r  = i % ((HID / 4) * DPC);
        int kq = r / DPC;
        int dd = r % DPC;
        const float* W = (g == 0) ? Whz : ((g == 1) ? Whr : Whh);
        float4 v;
        v.x = W[(kq * 4 + 0) * HID + dim0 + dd];
        v.y = W[(kq * 4 + 1) * HID + dim0 + dd];
        v.z = W[(kq * 4 + 2) * HID + dim0 + dd];
        v.w = W[(kq * 4 + 3) * HID + dim0 + dd];
        s->Wq[g][kq][dd] = v;
    }
    if (tid < BPC * (HID / 4)) {
        int bb = tid >> 6;
        int kq = tid & 63;
        s->hq[bb][kq] = *reinterpret_cast<const float4*>(&H0[(cid * BPC + bb) * HID + kq * 4]);
    }
    // one-time token preload (removes per-step flushed-L1 LDG of X)
    for (int i = tid; i < BPC * STEPS; i += FTH) {
        int bb = i / STEPS;
        int tt = i % STEPS;
        s->xs[bb][tt] = X[(cid * BPC + bb) * STEPS + tt];
    }
    const float bzv = bz[dim];
    const float brv = br[dim];
    const float bhv = bh[dim];
    __syncthreads();
    CLUSTER_SYNC();   // weights + h0 + xs visible cluster-wide (once, off hot loop)

    // hoisted remote-store addresses (loop-invariant mapa)
    const uint32_t rh_l = sptr(&reinterpret_cast<float*>(s->rhq)[b * HID + dim]);
    const uint32_t h_l  = sptr(&reinterpret_cast<float*>(s->hq)[b * HID + dim]);
    uint32_t rh_rem[CLUSTER], h_rem[CLUSTER];
    #pragma unroll
    for (int rr = 0; rr < CLUSTER; ++rr) {
        rh_rem[rr] = mapa_rank(rh_l, rr);
        h_rem[rr]  = mapa_rank(h_l, rr);
    }

    // initial gather prefetch for t=0 (values live in registers, flush-immune)
    float pxz = 0.f, pxr = 0.f, pxh = 0.f;
    if (active) {
        int xv0 = s->xs[b][0];
        pxz = Wxz[xv0 * HID + dim];
        pxr = Wxr[xv0 * HID + dim];
        pxh = Wxh[xv0 * HID + dim];
    }

    #pragma unroll 1
    for (int t = 0; t < STEPS; ++t) {
        float zv = 0.f, hold = 0.f, xh = 0.f;   // carried in registers across sync

        if (active) {
            float xz = pxz;
            float xr = pxr;
            xh = pxh;
            hold = reinterpret_cast<const float*>(s->hq)[b * HID + dim];

            unsigned long long az0 = 0ull, az1 = 0ull, ar0 = 0ull, ar1 = 0ull;
            const ulonglong2* wz = reinterpret_cast<const ulonglong2*>(&s->Wq[0][0][d]);
            const ulonglong2* wr = reinterpret_cast<const ulonglong2*>(&s->Wq[1][0][d]);
            const ulonglong2* hp = reinterpret_cast<const ulonglong2*>(&s->hq[b][0]);
            #pragma unroll 16
            for (int kq = 0; kq < HID / 4; ++kq) {
                ulonglong2 h2 = hp[kq];
                ulonglong2 a  = wz[kq * DPC];
                ulonglong2 c  = wr[kq * DPC];
                FMA2(az0, a.x, h2.x); FMA2(az1, a.y, h2.y);
                FMA2(ar0, c.x, h2.x); FMA2(ar1, c.y, h2.y);
            }
            float2 z0 = unpack2(az0), z1 = unpack2(az1);
            float2 r0 = unpack2(ar0), r1 = unpack2(ar1);
            zv = fast_sigmoid(((z0.x + z0.y) + (z1.x + z1.y)) + xz + bzv);
            float rv = fast_sigmoid(((r0.x + r0.y) + (r1.x + r1.y)) + xr + brv);
            float rh = rv * hold;
            #pragma unroll
            for (int rr = 0; rr < CLUSTER; ++rr) st_cluster_addr(rh_rem[rr], rh);
        }
        // ---- sync 1 with useful work inside the wait window ----
        CLUSTER_ARRIVE();
        if (active) {
            // prefetch next step's gathers; touches only xs (not cluster-protected)
            int tn  = (t + 1 < STEPS) ? (t + 1) : t;
            int xvn = s->xs[b][tn];
            pxz = Wxz[xvn * HID + dim];
            pxr = Wxr[xvn * HID + dim];
            pxh = Wxh[xvn * HID + dim];
        }
        CLUSTER_WAIT();

        if (active) {
            unsigned long long ah0 = 0ull, ah1 = 0ull;
            const ulonglong2* wh = reinterpret_cast<const ulonglong2*>(&s->Wq[2][0][d]);
            const ulonglong2* rp = reinterpret_cast<const ulonglong2*>(&s->rhq[b][0]);
            #pragma unroll 16
            for (int kq = 0; kq < HID / 4; ++kq) {
                ulonglong2 r2 = rp[kq];
                ulonglong2 a  = wh[kq * DPC];
                FMA2(ah0, a.x, r2.x); FMA2(ah1, a.y, r2.y);
            }
            float2 h0 = unpack2(ah0), h1 = unpack2(ah1);
            float htl  = fast_tanh(((h0.x + h0.y) + (h1.x + h1.y)) + xh + bhv);
            float hnew = zv * hold + (1.f - zv) * htl;
            #pragma unroll
            for (int rr = 0; rr < CLUSTER; ++rr) st_cluster_addr(h_rem[rr], hnew);

            int row = t * BATCH + bg;
            __nv_bfloat16 hb = __float2bfloat16(hnew);
            g_Ahi[row * HID + dim] = hb;
            g_Alo[row * HID + dim] = __float2bfloat16(hnew - __bfloat162float(hb));
            if (t == STEPS - 1) outF[bg * HID + dim] = hnew;
        }
        CLUSTER_SYNC();
        if (tid == 0) st_rel(&g_prog[blockIdx.x], (unsigned)(t + 1));
    }
}

// ================= GEMM body (round-3 logic, smem from dynamic buffer) =================
#define CP16(dst, src, sz) \
    asm volatile("cp.async.cg.shared.global [%0], [%1], 16, %2;" :: "r"(dst), "l"(src), "r"(sz))
#define LDSM4(r, addr) \
    asm volatile("ldmatrix.sync.aligned.m8n8.x4.shared.b16 {%0,%1,%2,%3}, [%4];" \
        : "=r"((r)[0]), "=r"((r)[1]), "=r"((r)[2]), "=r"((r)[3]) : "r"(addr))
#define LDSMT2(r, addr) \
    asm volatile("ldmatrix.sync.aligned.m8n8.x2.trans.shared.b16 {%0,%1}, [%2];" \
        : "=r"((r)[0]), "=r"((r)[1]) : "r"(addr))
#define MMA16816(d, a, b) \
    asm volatile("mma.sync.aligned.m16n8k16.row.col.f32.bf16.bf16.f32 " \
        "{%0,%1,%2,%3}, {%4,%5,%6,%7}, {%8,%9}, {%0,%1,%2,%3};" \
        : "+f"((d)[0]), "+f"((d)[1]), "+f"((d)[2]), "+f"((d)[3]) \
        : "r"((a)[0]), "r"((a)[1]), "r"((a)[2]), "r"((a)[3]), "r"((b)[0]), "r"((b)[1]))

__device__ void gemm_body(int g, const float* __restrict__ bias, float* __restrict__ C)
{
    GSmem* gs = reinterpret_cast<GSmem*>(dyn_smem);
    const int tid  = threadIdx.x;
    const int lane = tid & 31;
    const int warp = tid >> 5;
    const int wm   = (warp >> 2) * 64;
    const int wn   = (warp & 3) * 32;
    const int mtile = g / NTN;
    const int ntile = g % NTN;
    const int m0   = mtile * GBM;
    const int n0   = ntile * GBN;

    // ---- band wait: all 64 recurrence CTAs past step 4*mtile+3 ----
    const unsigned need = (unsigned)(mtile * 4 + 4);
    if (tid < NREC) {
        while (ld_acq(&g_prog[tid]) < need) __nanosleep(256);
    }
    __syncthreads();

    float acc[4][4][4];
    #pragma unroll
    for (int i = 0; i < 4; ++i)
        #pragma unroll
        for (int j = 0; j < 4; ++j)
            #pragma unroll
            for (int q = 0; q < 4; ++q) acc[i][j][q] = 0.f;

    auto load_stage = [&](int st, int k0) {
        #pragma unroll
        for (int i = 0; i < 2; ++i) {
            int idx = tid + (i << 8);
            int sel = idx >> 8;
            int r   = idx & 255;
            int m   = r >> 1;
            int ku  = r & 1;
            const __nv_bfloat16* gp = (sel ? g_Alo : g_Ahi) + (size_t)(m0 + m) * HID + k0 + ku * 8;
            uint32_t dd = sptr(sel ? gs->Al[st] : gs->Ah[st]) + m * 32 + ((ku ^ ((m >> 2) & 1)) << 4);
            CP16(dd, gp, 16);
        }
        #pragma unroll
        for (int i = 0; i < 2; ++i) {
            int idx = tid + (i << 8);
            int sel = idx >> 8;
            int r   = idx & 255;
            int k   = r >> 4;
            int nu  = r & 15;
            int col = n0 + nu * 8;
            const __nv_bfloat16* gp = (sel ? g_Blo : g_Bhi) + (size_t)(k0 + k) * VOCAB + col;
            uint32_t dd = sptr(sel ? gs->Bl[st] : gs->Bh[st]) + k * 256 + ((nu ^ (k & 7)) << 4);
            int sz = (col + 8 <= VOCAB) ? 16 : 0;
            CP16(dd, gp, sz);
        }
    };

    load_stage(0, 0);
    asm volatile("cp.async.commit_group;");

    const int lrow = lane & 15;
    const int lkb  = (lane >> 4) & 1;

    #pragma unroll 1
    for (int c = 0; c < GNC; ++c) {
        if (c + 1 < GNC) load_stage((c + 1) & 1, (c + 1) * GBK);
        asm volatile("cp.async.commit_group;");
        asm volatile("cp.async.wait_group 1;");
        __syncthreads();

        const int st = c & 1;
        uint32_t ah[4][4], al[4][4], bh[4][2], bl[4][2];
        #pragma unroll
        for (int mt = 0; mt < 4; ++mt) {
            int m = wm + mt * 16 + lrow;
            uint32_t off = m * 32 + ((lkb ^ ((m >> 2) & 1)) << 4);
            LDSM4(ah[mt], sptr(gs->Ah[st]) + off);
            LDSM4(al[mt], sptr(gs->Al[st]) + off);
        }
        #pragma unroll
        for (int nt = 0; nt < 4; ++nt) {
            int k = lrow;
            int n = wn + nt * 8;
            uint32_t off = k * 256 + (((n >> 3) ^ (k & 7)) << 4);
            LDSMT2(bh[nt], sptr(gs->Bh[st]) + off);
            LDSMT2(bl[nt], sptr(gs->Bl[st]) + off);
        }
        #pragma unroll
        for (int mt = 0; mt < 4; ++mt)
            #pragma unroll
            for (int nt = 0; nt < 4; ++nt) {
                MMA16816(acc[mt][nt], ah[mt], bh[nt]);
                MMA16816(acc[mt][nt], ah[mt], bl[nt]);
                MMA16816(acc[mt][nt], al[mt], bh[nt]);
            }
        __syncthreads();
    }

    #pragma unroll
    for (int nt = 0; nt < 4; ++nt) {
        int cbase = n0 + wn + nt * 8 + 2 * (lane & 3);
        float2 bv = make_float2(0.f, 0.f);
        if (cbase + 1 < VOCAB) bv = *reinterpret_cast<const float2*>(bias + cbase);
        #pragma unroll
        for (int mt = 0; mt < 4; ++mt) {
            int r0 = m0 + wm + mt * 16 + (lane >> 2);
            if (cbase + 1 < VOCAB) {
                float2 v0 = make_float2(acc[mt][nt][0] + bv.x, acc[mt][nt][1] + bv.y);
                float2 v1 = make_float2(acc[mt][nt][2] + bv.x, acc[mt][nt][3] + bv.y);
                *reinterpret_cast<float2*>(C + (size_t)r0 * VOCAB + cbase) = v0;
                *reinterpret_cast<float2*>(C + (size_t)(r0 + 8) * VOCAB + cbase) = v1;
            }
        }
    }
}

// ================= fused kernel =================
__global__ __launch_bounds__(FTH, 1) __cluster_dims__(CLUSTER, 1, 1)
void fused_kernel(const int* __restrict__ X, const float* __restrict__ H0,
                  const float* __restrict__ Wxz, const float* __restrict__ Whz, const float* __restrict__ bz,
                  const float* __restrict__ Wxr, const float* __restrict__ Whr, const float* __restrict__ br,
                  const float* __restrict__ Wxh, const float* __restrict__ Whh, const float* __restrict__ bh,
                  const float* __restrict__ bq, float* __restrict__ C, float* __restrict__ outF)
{
    if (blockIdx.x < NREC) {
        rnn_body(X, H0, Wxz, Whz, bz, Wxr, Whr, br, Wxh, Whh, bh, outF);
    } else {
        gemm_body((int)blockIdx.x - NREC, bq, C);
    }
}

// ================= launch =================
extern "C" void kernel_launch(void* const* d_in, const int* in_sizes, int n_in,
                              void* d_out, int out_size) {
    const int*   X   = (const int*)  d_in[0];
    const float* H0  = (const float*)d_in[1];
    const float* Wxz = (const float*)d_in[2];
    const float* Whz = (const float*)d_in[3];
    const float* bz  = (const float*)d_in[4];
    const float* Wxr = (const float*)d_in[5];
    const float* Whr = (const float*)d_in[6];
    const float* br  = (const float*)d_in[7];
    const float* Wxh = (const float*)d_in[8];
    const float* Whh = (const float*)d_in[9];
    const float* bh  = (const float*)d_in[10];
    const float* Whq = (const float*)d_in[11];
    const float* bq  = (const float*)d_in[12];

    float* out  = (float*)d_out;
    float* outF = out + (out_size - BATCH * HID);

    static bool attr_set = false;
    if (!attr_set) {
        cudaFuncSetAttribute(fused_kernel, cudaFuncAttributeMaxDynamicSharedMemorySize,
                             (int)sizeof(RSmem));
        attr_set = true;
    }

    prog_reset_kernel<<<1, 64>>>();
    convB_kernel<<<(HID * VOCAB + 255) / 256, 256>>>(Whq);
    fused_kernel<<<NREC + NTM * NTN, FTH, sizeof(RSmem)>>>(
        X, H0, Wxz, Whz, bz, Wxr, Whr, br, Wxh, Whh, bh, bq, out, outF);
}

// round 15
// speedup vs baseline: 1.3514x; 1.0140x over previous
#include <cuda_runtime.h>
#include <cuda_bf16.h>
#include <cstdint>

#define BATCH 32
#define HID   256
#define VOCAB 10000
#define STEPS 256

// ---------------- config ----------------
#define CLUSTER 4
#define BPC     2
#define DPC     64
#define NREC    64                 // recurrence CTAs (bids 0..63, wave 1)
#define FTH     256                // threads per CTA (fused kernel)

#define GBM 128
#define GBN 128
#define GBK 16
#define GNC (HID / GBK)
#define NTN ((VOCAB + GBN - 1) / GBN)   // 79 N tiles
#define NTM ((STEPS * BATCH) / GBM)     // 64 M tiles

// ---------------- scratch (device globals: allocation-free) ----------------
__device__ __nv_bfloat16 g_Ahi[STEPS * BATCH * HID];
__device__ __nv_bfloat16 g_Alo[STEPS * BATCH * HID];
__device__ __nv_bfloat16 g_Bhi[HID * VOCAB];
__device__ __nv_bfloat16 g_Blo[HID * VOCAB];
__device__ unsigned g_prog[NREC];   // per-recurrence-CTA step progress (t+1)

__global__ void prog_reset_kernel() {
    if (threadIdx.x < NREC) g_prog[threadIdx.x] = 0u;
}

__global__ void convB_kernel(const float* __restrict__ W) {
    int i = blockIdx.x * 256 + threadIdx.x;
    if (i < HID * VOCAB) {
        float v = W[i];
        __nv_bfloat16 h = __float2bfloat16(v);
        g_Bhi[i] = h;
        g_Blo[i] = __float2bfloat16(v - __bfloat162float(h));
    }
}

__device__ __forceinline__ uint32_t sptr(const void* p) {
    return (uint32_t)__cvta_generic_to_shared(p);
}
__device__ __forceinline__ unsigned ld_acq(const unsigned* p) {
    unsigned v;
    asm volatile("ld.acquire.gpu.global.u32 %0, [%1];" : "=r"(v) : "l"(p) : "memory");
    return v;
}
__device__ __forceinline__ void st_rel(unsigned* p, unsigned v) {
    asm volatile("st.release.gpu.global.u32 [%0], %1;" :: "l"(p), "r"(v) : "memory");
}

#define FMA2(acc, a, b) \
    asm("fma.rn.f32x2 %0, %1, %2, %0;" : "+l"(acc) : "l"(a), "l"(b))

__device__ __forceinline__ float2 unpack2(unsigned long long v) {
    float2 f;
    asm("mov.b64 {%0, %1}, %2;" : "=f"(f.x), "=f"(f.y) : "l"(v));
    return f;
}

__device__ __forceinline__ uint32_t mapa_rank(uint32_t laddr, int rank) {
    uint32_t ra;
    asm("mapa.shared::cluster.u32 %0, %1, %2;" : "=r"(ra) : "r"(laddr), "r"(rank));
    return ra;
}
__device__ __forceinline__ void st_cluster_addr(uint32_t raddr, float v) {
    asm volatile("st.shared::cluster.f32 [%0], %1;" :: "r"(raddr), "f"(v) : "memory");
}

#define CLUSTER_ARRIVE() asm volatile("barrier.cluster.arrive.aligned;" ::: "memory")
#define CLUSTER_WAIT()   asm volatile("barrier.cluster.wait.aligned;"   ::: "memory")
#define CLUSTER_SYNC() do { CLUSTER_ARRIVE(); CLUSTER_WAIT(); } while (0)

// fast transcendentals: MUFU-based, rel err ~1e-6 (threshold 1e-3)
__device__ __forceinline__ float fast_sigmoid(float x) {
    float e = __expf(-x);
    return __fdividef(1.f, 1.f + e);
}
__device__ __forceinline__ float fast_tanh(float x) {
    float e = __expf(-2.f * x);
    return __fdividef(2.f, 1.f + e) - 1.f;
}

// ---------------- smem overlays (one dynamic buffer) ----------------
struct RSmem {                           // recurrence CTAs
    float4 Wq[3][HID / 4][DPC];          // 196608 B
    float4 hq[BPC][HID / 4];
    float4 rhq[BPC][HID / 4];
    int    xs[BPC][STEPS];               // preloaded tokens (survive L1 flush)
};
struct GSmem {                           // GEMM CTAs (32 KB region of same buffer)
    __nv_bfloat16 Ah[2][GBM * GBK];
    __nv_bfloat16 Al[2][GBM * GBK];
    __nv_bfloat16 Bh[2][GBK * GBN];
    __nv_bfloat16 Bl[2][GBK * GBN];
};

extern __shared__ __align__(16) char dyn_smem[];

// 16-kq partial of the z/r gate dots starting at float4-block `base`
__device__ __forceinline__ void dot16_zr(const ulonglong2* __restrict__ wz,
                                         const ulonglong2* __restrict__ wr,
                                         const ulonglong2* __restrict__ hp, int base,
                                         unsigned long long& az0, unsigned long long& az1,
                                         unsigned long long& ar0, unsigned long long& ar1)
{
    #pragma unroll
    for (int j = 0; j < 16; ++j) {
        int kq = base + j;
        ulonglong2 h2 = hp[kq];
        ulonglong2 a  = wz[kq * DPC];
        ulonglong2 c  = wr[kq * DPC];
        FMA2(az0, a.x, h2.x); FMA2(az1, a.y, h2.y);
        FMA2(ar0, c.x, h2.x); FMA2(ar1, c.y, h2.y);
    }
}

// 16-kq partial of the W_hh dot starting at float4-block `base`
__device__ __forceinline__ void dot16_h(const ulonglong2* __restrict__ wh,
                                        const ulonglong2* __restrict__ rp, int base,
                                        unsigned long long& a0, unsigned long long& a1)
{
    #pragma unroll
    for (int j = 0; j < 16; ++j) {
        int kq = base + j;
        ulonglong2 r2 = rp[kq];
        ulonglong2 a  = wh[kq * DPC];
        FMA2(a0, a.x, r2.x); FMA2(a1, a.y, r2.y);
    }
}

// ================= recurrence body (R14 + barrier-window dot partials) =================
__device__ void rnn_body(const int* __restrict__ X, const float* __restrict__ H0,
                         const float* __restrict__ Wxz, const float* __restrict__ Whz, const float* __restrict__ bz,
                         const float* __restrict__ Wxr, const float* __restrict__ Whr, const float* __restrict__ br,
                         const float* __restrict__ Wxh, const float* __restrict__ Whh, const float* __restrict__ bh,
                         float* __restrict__ outF)
{
    RSmem* s = reinterpret_cast<RSmem*>(dyn_smem);
    const int tid    = threadIdx.x;
    const bool active = tid < 128;
    const int rank = (int)(blockIdx.x & (CLUSTER - 1));
    const int cid  = (int)(blockIdx.x >> 2);
    const int dim0 = rank * DPC;
    const int b    = tid & 1;
    const int d    = active ? (tid >> 1) : 0;
    const int bg   = cid * BPC + b;
    const int dim  = dim0 + d;
    const int ownq = rank * 16;          // own 16-block of float4 k-range

    // one-time weight slice load (all 256 threads help)
    for (int i = tid; i < 3 * (HID / 4) * DPC; i += FTH) {
        int g  = i / ((HID / 4) * DPC);
        int r  = i % ((HID / 4) * DPC);
        int kq = r / DPC;
        int dd = r % DPC;
        const float* W = (g == 0) ? Whz : ((g == 1) ? Whr : Whh);
        float4 v;
        v.x = W[(kq * 4 + 0) * HID + dim0 + dd];
        v.y = W[(kq * 4 + 1) * HID + dim0 + dd];
        v.z = W[(kq * 4 + 2) * HID + dim0 + dd];
        v.w = W[(kq * 4 + 3) * HID + dim0 + dd];
        s->Wq[g][kq][dd] = v;
    }
    if (tid < BPC * (HID / 4)) {
        int bb = tid >> 6;
        int kq = tid & 63;
        s->hq[bb][kq] = *reinterpret_cast<const float4*>(&H0[(cid * BPC + bb) * HID + kq * 4]);
    }
    // one-time token preload (removes per-step flushed-L1 LDG of X)
    for (int i = tid; i < BPC * STEPS; i += FTH) {
        int bb = i / STEPS;
        int tt = i % STEPS;
        s->xs[bb][tt] = X[(cid * BPC + bb) * STEPS + tt];
    }
    const float bzv = bz[dim];
    const float brv = br[dim];
    const float bhv = bh[dim];
    __syncthreads();
    CLUSTER_SYNC();   // weights + h0 + xs visible cluster-wide (once, off hot loop)

    // hoisted remote-store addresses (loop-invariant mapa)
    const uint32_t rh_l = sptr(&reinterpret_cast<float*>(s->rhq)[b * HID + dim]);
    const uint32_t h_l  = sptr(&reinterpret_cast<float*>(s->hq)[b * HID + dim]);
    uint32_t rh_rem[CLUSTER], h_rem[CLUSTER];
    #pragma unroll
    for (int rr = 0; rr < CLUSTER; ++rr) {
        rh_rem[rr] = mapa_rank(rh_l, rr);
        h_rem[rr]  = mapa_rank(h_l, rr);
    }

    const ulonglong2* wz = reinterpret_cast<const ulonglong2*>(&s->Wq[0][0][d]);
    const ulonglong2* wr = reinterpret_cast<const ulonglong2*>(&s->Wq[1][0][d]);
    const ulonglong2* wh = reinterpret_cast<const ulonglong2*>(&s->Wq[2][0][d]);
    const ulonglong2* hp = reinterpret_cast<const ulonglong2*>(&s->hq[b][0]);
    const ulonglong2* rp = reinterpret_cast<const ulonglong2*>(&s->rhq[b][0]);

    // initial gather prefetch for t=0 (values live in registers, flush-immune)
    float pxz = 0.f, pxr = 0.f, pxh = 0.f;
    // phase-1 own-block partials for t=0 (h0 is complete after initial sync)
    unsigned long long p1z0 = 0ull, p1z1 = 0ull, p1r0 = 0ull, p1r1 = 0ull;
    if (active) {
        int xv0 = s->xs[b][0];
        pxz = Wxz[xv0 * HID + dim];
        pxr = Wxr[xv0 * HID + dim];
        pxh = Wxh[xv0 * HID + dim];
        dot16_zr(wz, wr, hp, ownq, p1z0, p1z1, p1r0, p1r1);
    }

    #pragma unroll 1
    for (int t = 0; t < STEPS; ++t) {
        float zv = 0.f, hold = 0.f, xh = 0.f;   // carried in registers across sync

        if (active) {
            float xz = pxz;
            float xr = pxr;
            xh = pxh;
            hold = reinterpret_cast<const float*>(s->hq)[b * HID + dim];

            // phase 1: remaining 3 blocks (own block already in p1*)
            unsigned long long az0 = p1z0, az1 = p1z1, ar0 = p1r0, ar1 = p1r1;
            #pragma unroll
            for (int j = 1; j < CLUSTER; ++j) {
                int base = (((rank + j) & (CLUSTER - 1)) * 16);
                dot16_zr(wz, wr, hp, base, az0, az1, ar0, ar1);
            }
            float2 z0 = unpack2(az0), z1 = unpack2(az1);
            float2 r0 = unpack2(ar0), r1 = unpack2(ar1);
            zv = fast_sigmoid(((z0.x + z0.y) + (z1.x + z1.y)) + xz + bzv);
            float rv = fast_sigmoid(((r0.x + r0.y) + (r1.x + r1.y)) + xr + brv);
            float rh = rv * hold;
            #pragma unroll
            for (int rr = 0; rr < CLUSTER; ++rr) st_cluster_addr(rh_rem[rr], rh);
        }
        __syncthreads();          // local rh (own dims) visible CTA-wide
        CLUSTER_ARRIVE();
        // ---- sync-1 window: gather prefetch + phase-2 own-block partial ----
        unsigned long long q0 = 0ull, q1 = 0ull;
        if (active) {
            int tn  = (t + 1 < STEPS) ? (t + 1) : t;
            int xvn = s->xs[b][tn];
            pxz = Wxz[xvn * HID + dim];
            pxr = Wxr[xvn * HID + dim];
            pxh = Wxh[xvn * HID + dim];
            dot16_h(wh, rp, ownq, q0, q1);    // own rh dims are local-produced
        }
        CLUSTER_WAIT();

        if (active) {
            // phase 2: remaining 3 blocks
            #pragma unroll
            for (int j = 1; j < CLUSTER; ++j) {
                int base = (((rank + j) & (CLUSTER - 1)) * 16);
                dot16_h(wh, rp, base, q0, q1);
            }
            float2 h0 = unpack2(q0), h1 = unpack2(q1);
            float htl  = fast_tanh(((h0.x + h0.y) + (h1.x + h1.y)) + xh + bhv);
            float hnew = zv * hold + (1.f - zv) * htl;
            #pragma unroll
            for (int rr = 0; rr < CLUSTER; ++rr) st_cluster_addr(h_rem[rr], hnew);

            int row = t * BATCH + bg;
            __nv_bfloat16 hb = __float2bfloat16(hnew);
            g_Ahi[row * HID + dim] = hb;
            g_Alo[row * HID + dim] = __float2bfloat16(hnew - __bfloat162float(hb));
            if (t == STEPS - 1) outF[bg * HID + dim] = hnew;
        }
        __syncthreads();          // local hnew (own dims) + g_A stores ordered
        CLUSTER_ARRIVE();
        // ---- sync-2 window: next step's phase-1 own-block partials ----
        p1z0 = 0ull; p1z1 = 0ull; p1r0 = 0ull; p1r1 = 0ull;
        if (active) {
            dot16_zr(wz, wr, hp, ownq, p1z0, p1z1, p1r0, p1r1);
        }
        CLUSTER_WAIT();
        if (tid == 0) st_rel(&g_prog[blockIdx.x], (unsigned)(t + 1));
    }
}

// ================= GEMM body (round-3 logic, smem from dynamic buffer) =================
#define CP16(dst, src, sz) \
    asm volatile("cp.async.cg.shared.global [%0], [%1], 16, %2;" :: "r"(dst), "l"(src), "r"(sz))
#define LDSM4(r, addr) \
    asm volatile("ldmatrix.sync.aligned.m8n8.x4.shared.b16 {%0,%1,%2,%3}, [%4];" \
        : "=r"((r)[0]), "=r"((r)[1]), "=r"((r)[2]), "=r"((r)[3]) : "r"(addr))
#define LDSMT2(r, addr) \
    asm volatile("ldmatrix.sync.aligned.m8n8.x2.trans.shared.b16 {%0,%1}, [%2];" \
        : "=r"((r)[0]), "=r"((r)[1]) : "r"(addr))
#define MMA16816(d, a, b) \
    asm volatile("mma.sync.aligned.m16n8k16.row.col.f32.bf16.bf16.f32 " \
        "{%0,%1,%2,%3}, {%4,%5,%6,%7}, {%8,%9}, {%0,%1,%2,%3};" \
        : "+f"((d)[0]), "+f"((d)[1]), "+f"((d)[2]), "+f"((d)[3]) \
        : "r"((a)[0]), "r"((a)[1]), "r"((a)[2]), "r"((a)[3]), "r"((b)[0]), "r"((b)[1]))

__device__ void gemm_body(int g, const float* __restrict__ bias, float* __restrict__ C)
{
    GSmem* gs = reinterpret_cast<GSmem*>(dyn_smem);
    const int tid  = threadIdx.x;
    const int lane = tid & 31;
    const int warp = tid >> 5;
    const int wm   = (warp >> 2) * 64;
    const int wn   = (warp & 3) * 32;
    const int mtile = g / NTN;
    const int ntile = g % NTN;
    const int m0   = mtile * GBM;
    const int n0   = ntile * GBN;

    // ---- band wait: all 64 recurrence CTAs past step 4*mtile+3 ----
    const unsigned need = (unsigned)(mtile * 4 + 4);
    if (tid < NREC) {
        while (ld_acq(&g_prog[tid]) < need) __nanosleep(256);
    }
    __syncthreads();

    float acc[4][4][4];
    #pragma unroll
    for (int i = 0; i < 4; ++i)
        #pragma unroll
        for (int j = 0; j < 4; ++j)
            #pragma unroll
            for (int q = 0; q < 4; ++q) acc[i][j][q] = 0.f;

    auto load_stage = [&](int st, int k0) {
        #pragma unroll
        for (int i = 0; i < 2; ++i) {
            int idx = tid + (i << 8);
            int sel = idx >> 8;
            int r   = idx & 255;
            int m   = r >> 1;
            int ku  = r & 1;
            const __nv_bfloat16* gp = (sel ? g_Alo : g_Ahi) + (size_t)(m0 + m) * HID + k0 + ku * 8;
            uint32_t dd = sptr(sel ? gs->Al[st] : gs->Ah[st]) + m * 32 + ((ku ^ ((m >> 2) & 1)) << 4);
            CP16(dd, gp, 16);
        }
        #pragma unroll
        for (int i = 0; i < 2; ++i) {
            int idx = tid + (i << 8);
            int sel = idx >> 8;
            int r   = idx & 255;
            int k   = r >> 4;
            int nu  = r & 15;
            int col = n0 + nu * 8;
            const __nv_bfloat16* gp = (sel ? g_Blo : g_Bhi) + (size_t)(k0 + k) * VOCAB + col;
            uint32_t dd = sptr(sel ? gs->Bl[st] : gs->Bh[st]) + k * 256 + ((nu ^ (k & 7)) << 4);
            int sz = (col + 8 <= VOCAB) ? 16 : 0;
            CP16(dd, gp, sz);
        }
    };

    load_stage(0, 0);
    asm volatile("cp.async.commit_group;");

    const int lrow = lane & 15;
    const int lkb  = (lane >> 4) & 1;

    #pragma unroll 1
    for (int c = 0; c < GNC; ++c) {
        if (c + 1 < GNC) load_stage((c + 1) & 1, (c + 1) * GBK);
        asm volatile("cp.async.commit_group;");
        asm volatile("cp.async.wait_group 1;");
        __syncthreads();

        const int st = c & 1;
        uint32_t ah[4][4], al[4][4], bh[4][2], bl[4][2];
        #pragma unroll
        for (int mt = 0; mt < 4; ++mt) {
            int m = wm + mt * 16 + lrow;
            uint32_t off = m * 32 + ((lkb ^ ((m >> 2) & 1)) << 4);
            LDSM4(ah[mt], sptr(gs->Ah[st]) + off);
            LDSM4(al[mt], sptr(gs->Al[st]) + off);
        }
        #pragma unroll
        for (int nt = 0; nt < 4; ++nt) {
            int k = lrow;
            int n = wn + nt * 8;
            uint32_t off = k * 256 + (((n >> 3) ^ (k & 7)) << 4);
            LDSMT2(bh[nt], sptr(gs->Bh[st]) + off);
            LDSMT2(bl[nt], sptr(gs->Bl[st]) + off);
        }
        #pragma unroll
        for (int mt = 0; mt < 4; ++mt)
            #pragma unroll
            for (int nt = 0; nt < 4; ++nt) {
                MMA16816(acc[mt][nt], ah[mt], bh[nt]);
                MMA16816(acc[mt][nt], ah[mt], bl[nt]);
                MMA16816(acc[mt][nt], al[mt], bh[nt]);
            }
        __syncthreads();
    }

    #pragma unroll
    for (int nt = 0; nt < 4; ++nt) {
        int cbase = n0 + wn + nt * 8 + 2 * (lane & 3);
        float2 bv = make_float2(0.f, 0.f);
        if (cbase + 1 < VOCAB) bv = *reinterpret_cast<const float2*>(bias + cbase);
        #pragma unroll
        for (int mt = 0; mt < 4; ++mt) {
            int r0 = m0 + wm + mt * 16 + (lane >> 2);
            if (cbase + 1 < VOCAB) {
                float2 v0 = make_float2(acc[mt][nt][0] + bv.x, acc[mt][nt][1] + bv.y);
                float2 v1 = make_float2(acc[mt][nt][2] + bv.x, acc[mt][nt][3] + bv.y);
                *reinterpret_cast<float2*>(C + (size_t)r0 * VOCAB + cbase) = v0;
                *reinterpret_cast<float2*>(C + (size_t)(r0 + 8) * VOCAB + cbase) = v1;
            }
        }
    }
}

// ================= fused kernel =================
__global__ __launch_bounds__(FTH, 1) __cluster_dims__(CLUSTER, 1, 1)
void fused_kernel(const int* __restrict__ X, const float* __restrict__ H0,
                  const float* __restrict__ Wxz, const float* __restrict__ Whz, const float* __restrict__ bz,
                  const float* __restrict__ Wxr, const float* __restrict__ Whr, const float* __restrict__ br,
                  const float* __restrict__ Wxh, const float* __restrict__ Whh, const float* __restrict__ bh,
                  const float* __restrict__ bq, float* __restrict__ C, float* __restrict__ outF)
{
    if (blockIdx.x < NREC) {
        rnn_body(X, H0, Wxz, Whz, bz, Wxr, Whr, br, Wxh, Whh, bh, outF);
    } else {
        gemm_body((int)blockIdx.x - NREC, bq, C);
    }
}

// ================= launch =================
extern "C" void kernel_launch(void* const* d_in, const int* in_sizes, int n_in,
                              void* d_out, int out_size) {
    const int*   X   = (const int*)  d_in[0];
    const float* H0  = (const float*)d_in[1];
    const float* Wxz = (const float*)d_in[2];
    const float* Whz = (const float*)d_in[3];
    const float* bz  = (const float*)d_in[4];
    const float* Wxr = (const float*)d_in[5];
    const float* Whr = (const float*)d_in[6];
    const float* br  = (const float*)d_in[7];
    const float* Wxh = (const float*)d_in[8];
    const float* Whh = (const float*)d_in[9];
    const float* bh  = (const float*)d_in[10];
    const float* Whq = (const float*)d_in[11];
    const float* bq  = (const float*)d_in[12];

    float* out  = (float*)d_out;
    float* outF = out + (out_size - BATCH * HID);

    static bool attr_set = false;
    if (!attr_set) {
        cudaFuncSetAttribute(fused_kernel, cudaFuncAttributeMaxDynamicSharedMemorySize,
                             (int)sizeof(RSmem));
        attr_set = true;
    }

    prog_reset_kernel<<<1, 64>>>();
    convB_kernel<<<(HID * VOCAB + 255) / 256, 256>>>(Whq);
    fused_kernel<<<NREC + NTM * NTN, FTH, sizeof(RSmem)>>>(
        X, H0, Wxz, Whz, bz, Wxr, Whr, br, Wxh, Whh, bh, bq, out, outF);
}

// round 16
// speedup vs baseline: 1.4206x; 1.0513x over previous
#include <cuda_runtime.h>
#include <cuda_bf16.h>
#include <cstdint>

#define BATCH 32
#define HID   256
#define VOCAB 10000
#define STEPS 256

// ---------------- config ----------------
#define CLUSTER 4
#define BPC     2
#define KOWN    64                 // own k-rows per CTA (HID/CLUSTER)
#define NREC    64                 // recurrence CTAs (bids 0..63, wave 1)
#define FTH     256                // threads per CTA (fused kernel)

#define GBM 128
#define GBN 128
#define GBK 16
#define GNC (HID / GBK)
#define NTN ((VOCAB + GBN - 1) / GBN)   // 79 N tiles
#define NTM ((STEPS * BATCH) / GBM)     // 64 M tiles

// ---------------- scratch (device globals: allocation-free) ----------------
__device__ __nv_bfloat16 g_Ahi[STEPS * BATCH * HID];
__device__ __nv_bfloat16 g_Alo[STEPS * BATCH * HID];
__device__ __nv_bfloat16 g_Bhi[HID * VOCAB];
__device__ __nv_bfloat16 g_Blo[HID * VOCAB];
__device__ unsigned g_prog[NREC];   // per-recurrence-CTA step progress (t+1)

__global__ void prog_reset_kernel() {
    if (threadIdx.x < NREC) g_prog[threadIdx.x] = 0u;
}

__global__ void convB_kernel(const float* __restrict__ W) {
    int i = blockIdx.x * 256 + threadIdx.x;
    if (i < HID * VOCAB) {
        float v = W[i];
        __nv_bfloat16 h = __float2bfloat16(v);
        g_Bhi[i] = h;
        g_Blo[i] = __float2bfloat16(v - __bfloat162float(h));
    }
}

__device__ __forceinline__ uint32_t sptr(const void* p) {
    return (uint32_t)__cvta_generic_to_shared(p);
}
__device__ __forceinline__ unsigned ld_acq(const unsigned* p) {
    unsigned v;
    asm volatile("ld.acquire.gpu.global.u32 %0, [%1];" : "=r"(v) : "l"(p) : "memory");
    return v;
}
__device__ __forceinline__ void st_rel(unsigned* p, unsigned v) {
    asm volatile("st.release.gpu.global.u32 [%0], %1;" :: "l"(p), "r"(v) : "memory");
}

#define FMA2(acc, a, b) \
    asm("fma.rn.f32x2 %0, %1, %2, %0;" : "+l"(acc) : "l"(a), "l"(b))

__device__ __forceinline__ unsigned long long pack2(float x) {
    unsigned long long v;
    unsigned u = __float_as_uint(x);
    asm("mov.b64 %0, {%1, %1};" : "=l"(v) : "r"(u));
    return v;
}

__device__ __forceinline__ uint32_t mapa_rank(uint32_t laddr, int rank) {
    uint32_t ra;
    asm("mapa.shared::cluster.u32 %0, %1, %2;" : "=r"(ra) : "r"(laddr), "r"(rank));
    return ra;
}
__device__ __forceinline__ void st_cluster_b64(uint32_t raddr, unsigned long long v) {
    asm volatile("st.shared::cluster.b64 [%0], %1;" :: "r"(raddr), "l"(v) : "memory");
}

#define CLUSTER_ARRIVE() asm volatile("barrier.cluster.arrive.aligned;" ::: "memory")
#define CLUSTER_WAIT()   asm volatile("barrier.cluster.wait.aligned;"   ::: "memory")
#define CLUSTER_SYNC() do { CLUSTER_ARRIVE(); CLUSTER_WAIT(); } while (0)

// fast transcendentals: MUFU-based, rel err ~1e-6 (threshold 1e-3)
__device__ __forceinline__ float fast_sigmoid(float x) {
    float e = __expf(-x);
    return __fdividef(1.f, 1.f + e);
}
__device__ __forceinline__ float fast_tanh(float x) {
    float e = __expf(-2.f * x);
    return __fdividef(2.f, 1.f + e) - 1.f;
}

// ---------------- smem overlays (one dynamic buffer) ----------------
// Weight layout: Wq[g][k][cc] = float4 of W[g][rank*64+k][4cc..4cc+3]
//   (own 64 k-rows, ALL 256 d columns) -> partials computable from local data.
struct RSmem {
    float4 Wq[3][KOWN][HID / 4];                 // 196608 B
    float  part_zr[CLUSTER][BPC][2][KOWN];       // 4 KB   [src][b][gate][own dim]
    float  part_h[CLUSTER][BPC][KOWN];           // 2 KB   [src][b][own dim]
    float  h_loc[BPC][KOWN];                     // 512 B  own-dim h
    float  rh_loc[BPC][KOWN];                    // 512 B  own-dim r*h
    int    xs[BPC][STEPS];                       // 2 KB   preloaded tokens
};
struct GSmem {                                   // GEMM CTAs (32 KB region)
    __nv_bfloat16 Ah[2][GBM * GBK];
    __nv_bfloat16 Al[2][GBM * GBK];
    __nv_bfloat16 Bh[2][GBK * GBN];
    __nv_bfloat16 Bl[2][GBK * GBN];
};

extern __shared__ __align__(16) char dyn_smem[];

// ================= recurrence body (partial-sum exchange dataflow) =================
__device__ void rnn_body(const int* __restrict__ X, const float* __restrict__ H0,
                         const float* __restrict__ Wxz, const float* __restrict__ Whz, const float* __restrict__ bz,
                         const float* __restrict__ Wxr, const float* __restrict__ Whr, const float* __restrict__ br,
                         const float* __restrict__ Wxh, const float* __restrict__ Whh, const float* __restrict__ bh,
                         float* __restrict__ outF)
{
    RSmem* s = reinterpret_cast<RSmem*>(dyn_smem);
    const int tid    = threadIdx.x;
    const bool active = tid < 128;
    const int rank = (int)(blockIdx.x & (CLUSTER - 1));
    const int cid  = (int)(blockIdx.x >> 2);
    const int b    = tid & 1;
    const int c    = active ? (tid >> 1) : 0;    // own-dim index / partial column quad
    const int bg   = cid * BPC + b;
    const int dim  = rank * KOWN + c;            // global dim owned by this thread

    // one-time weight load: own 64 k-rows x all 256 cols (direct float4, coalesced)
    for (int i = tid; i < 3 * KOWN * (HID / 4); i += FTH) {
        int g  = i / (KOWN * (HID / 4));
        int r  = i % (KOWN * (HID / 4));
        int k  = r >> 6;
        int cc = r & 63;
        const float* W = (g == 0) ? Whz : ((g == 1) ? Whr : Whh);
        s->Wq[g][k][cc] = *reinterpret_cast<const float4*>(&W[(rank * KOWN + k) * HID + 4 * cc]);
    }
    if (active) s->h_loc[b][c] = H0[bg * HID + dim];
    for (int i = tid; i < BPC * STEPS; i += FTH) {
        int bb = i / STEPS;
        int tt = i % STEPS;
        s->xs[bb][tt] = X[(cid * BPC + bb) * STEPS + tt];
    }
    const float bzv = bz[dim];
    const float brv = br[dim];
    const float bhv = bh[dim];
    __syncthreads();
    CLUSTER_SYNC();   // weights + h0 + xs ready cluster-wide (once, off hot loop)

    // remote partial-store addresses (one mapa per buffer; target rank fixed)
    const int rt = c >> 4;            // CTA owning dims 4c..4c+3
    const int cl = c & 15;
    uint32_t pz_r = 0, pr_r = 0, ph_r = 0;
    if (active) {
        uint32_t mzr = mapa_rank(sptr(&s->part_zr[rank][b][0][0]), rt);
        pz_r = mzr + 16u * cl;                         // z-gate floats [4cl..4cl+3]
        pr_r = mzr + (KOWN * 4) + 16u * cl;            // r-gate (stride 64 floats)
        ph_r = mapa_rank(sptr(&s->part_h[rank][b][0]), rt) + 16u * cl;
    }

    const ulonglong2* wz = reinterpret_cast<const ulonglong2*>(&s->Wq[0][0][c]);
    const ulonglong2* wr = reinterpret_cast<const ulonglong2*>(&s->Wq[1][0][c]);
    const ulonglong2* wh = reinterpret_cast<const ulonglong2*>(&s->Wq[2][0][c]);

    // initial gather prefetch for t=0 (registers, flush-immune)
    float pxz = 0.f, pxr = 0.f, pxh = 0.f;
    if (active) {
        int xv0 = s->xs[b][0];
        pxz = Wxz[xv0 * HID + dim];
        pxr = Wxr[xv0 * HID + dim];
        pxh = Wxh[xv0 * HID + dim];
    }

    #pragma unroll 1
    for (int t = 0; t < STEPS; ++t) {
        float zv = 0.f, hold = 0.f, xh = 0.f, xz = 0.f, xr = 0.f;

        // ---- A: z/r partials over OWN k-range (local h only) ----
        if (active) {
            xz = pxz; xr = pxr; xh = pxh;
            hold = s->h_loc[b][c];
            const float* hl = s->h_loc[b];
            unsigned long long az0 = 0ull, az1 = 0ull, ar0 = 0ull, ar1 = 0ull;
            #pragma unroll 8
            for (int k = 0; k < KOWN; ++k) {
                unsigned long long h2 = pack2(hl[k]);
                ulonglong2 a  = wz[k * (HID / 4)];
                ulonglong2 cc = wr[k * (HID / 4)];
                FMA2(az0, a.x, h2); FMA2(az1, a.y, h2);
                FMA2(ar0, cc.x, h2); FMA2(ar1, cc.y, h2);
            }
            st_cluster_b64(pz_r, az0); st_cluster_b64(pz_r + 8, az1);
            st_cluster_b64(pr_r, ar0); st_cluster_b64(pr_r + 8, ar1);
        }
        CLUSTER_ARRIVE();
        if (active) {   // sync-1 window: next step's gather prefetch
            int tn  = (t + 1 < STEPS) ? (t + 1) : t;
            int xvn = s->xs[b][tn];
            pxz = Wxz[xvn * HID + dim];
            pxr = Wxr[xvn * HID + dim];
            pxh = Wxh[xvn * HID + dim];
        }
        CLUSTER_WAIT();

        // ---- D: finalize gates (4-way add + sigmoid), produce own rh ----
        if (active) {
            float zp = 0.f, rp = 0.f;
            #pragma unroll
            for (int src = 0; src < CLUSTER; ++src) {
                zp += s->part_zr[src][b][0][c];
                rp += s->part_zr[src][b][1][c];
            }
            zv = fast_sigmoid(zp + xz + bzv);
            float rv = fast_sigmoid(rp + xr + brv);
            s->rh_loc[b][c] = rv * hold;
        }
        __syncthreads();   // rh_loc visible CTA-wide

        // ---- E: h~ partial over OWN k-range (local rh only) ----
        if (active) {
            const float* rl = s->rh_loc[b];
            unsigned long long a0 = 0ull, a1 = 0ull;
            #pragma unroll 8
            for (int k = 0; k < KOWN; ++k) {
                unsigned long long r2 = pack2(rl[k]);
                ulonglong2 a = wh[k * (HID / 4)];
                FMA2(a0, a.x, r2); FMA2(a1, a.y, r2);
            }
            st_cluster_b64(ph_r, a0); st_cluster_b64(ph_r + 8, a1);
        }
        CLUSTER_ARRIVE();
        CLUSTER_WAIT();

        // ---- G: finalize h ----
        if (active) {
            float hp = 0.f;
            #pragma unroll
            for (int src = 0; src < CLUSTER; ++src) hp += s->part_h[src][b][c];
            float htl  = fast_tanh(hp + xh + bhv);
            float hnew = zv * hold + (1.f - zv) * htl;
            s->h_loc[b][c] = hnew;

            int row = t * BATCH + bg;
            __nv_bfloat16 hb = __float2bfloat16(hnew);
            g_Ahi[row * HID + dim] = hb;
            g_Alo[row * HID + dim] = __float2bfloat16(hnew - __bfloat162float(hb));
            if (t == STEPS - 1) outF[bg * HID + dim] = hnew;
        }
        __syncthreads();   // h_loc for next A; orders g_A before prog release
        if (tid == 0) st_rel(&g_prog[blockIdx.x], (unsigned)(t + 1));
    }
}

// ================= GEMM body (round-3 logic, smem from dynamic buffer) =================
#define CP16(dst, src, sz) \
    asm volatile("cp.async.cg.shared.global [%0], [%1], 16, %2;" :: "r"(dst), "l"(src), "r"(sz))
#define LDSM4(r, addr) \
    asm volatile("ldmatrix.sync.aligned.m8n8.x4.shared.b16 {%0,%1,%2,%3}, [%4];" \
        : "=r"((r)[0]), "=r"((r)[1]), "=r"((r)[2]), "=r"((r)[3]) : "r"(addr))
#define LDSMT2(r, addr) \
    asm volatile("ldmatrix.sync.aligned.m8n8.x2.trans.shared.b16 {%0,%1}, [%2];" \
        : "=r"((r)[0]), "=r"((r)[1]) : "r"(addr))
#define MMA16816(d, a, b) \
    asm volatile("mma.sync.aligned.m16n8k16.row.col.f32.bf16.bf16.f32 " \
        "{%0,%1,%2,%3}, {%4,%5,%6,%7}, {%8,%9}, {%0,%1,%2,%3};" \
        : "+f"((d)[0]), "+f"((d)[1]), "+f"((d)[2]), "+f"((d)[3]) \
        : "r"((a)[0]), "r"((a)[1]), "r"((a)[2]), "r"((a)[3]), "r"((b)[0]), "r"((b)[1]))

__device__ void gemm_body(int g, const float* __restrict__ bias, float* __restrict__ C)
{
    GSmem* gs = reinterpret_cast<GSmem*>(dyn_smem);
    const int tid  = threadIdx.x;
    const int lane = tid & 31;
    const int warp = tid >> 5;
    const int wm   = (warp >> 2) * 64;
    const int wn   = (warp & 3) * 32;
    const int mtile = g / NTN;
    const int ntile = g % NTN;
    const int m0   = mtile * GBM;
    const int n0   = ntile * GBN;

    // ---- band wait: all 64 recurrence CTAs past step 4*mtile+3 ----
    const unsigned need = (unsigned)(mtile * 4 + 4);
    if (tid < NREC) {
        while (ld_acq(&g_prog[tid]) < need) __nanosleep(256);
    }
    __syncthreads();

    float acc[4][4][4];
    #pragma unroll
    for (int i = 0; i < 4; ++i)
        #pragma unroll
        for (int j = 0; j < 4; ++j)
            #pragma unroll
            for (int q = 0; q < 4; ++q) acc[i][j][q] = 0.f;

    auto load_stage = [&](int st, int k0) {
        #pragma unroll
        for (int i = 0; i < 2; ++i) {
            int idx = tid + (i << 8);
            int sel = idx >> 8;
            int r   = idx & 255;
            int m   = r >> 1;
            int ku  = r & 1;
            const __nv_bfloat16* gp = (sel ? g_Alo : g_Ahi) + (size_t)(m0 + m) * HID + k0 + ku * 8;
            uint32_t dd = sptr(sel ? gs->Al[st] : gs->Ah[st]) + m * 32 + ((ku ^ ((m >> 2) & 1)) << 4);
            CP16(dd, gp, 16);
        }
        #pragma unroll
        for (int i = 0; i < 2; ++i) {
            int idx = tid + (i << 8);
            int sel = idx >> 8;
            int r   = idx & 255;
            int k   = r >> 4;
            int nu  = r & 15;
            int col = n0 + nu * 8;
            const __nv_bfloat16* gp = (sel ? g_Blo : g_Bhi) + (size_t)(k0 + k) * VOCAB + col;
            uint32_t dd = sptr(sel ? gs->Bl[st] : gs->Bh[st]) + k * 256 + ((nu ^ (k & 7)) << 4);
            int sz = (col + 8 <= VOCAB) ? 16 : 0;
            CP16(dd, gp, sz);
        }
    };

    load_stage(0, 0);
    asm volatile("cp.async.commit_group;");

    const int lrow = lane & 15;
    const int lkb  = (lane >> 4) & 1;

    #pragma unroll 1
    for (int c = 0; c < GNC; ++c) {
        if (c + 1 < GNC) load_stage((c + 1) & 1, (c + 1) * GBK);
        asm volatile("cp.async.commit_group;");
        asm volatile("cp.async.wait_group 1;");
        __syncthreads();

        const int st = c & 1;
        uint32_t ah[4][4], al[4][4], bh[4][2], bl[4][2];
        #pragma unroll
        for (int mt = 0; mt < 4; ++mt) {
            int m = wm + mt * 16 + lrow;
            uint32_t off = m * 32 + ((lkb ^ ((m >> 2) & 1)) << 4);
            LDSM4(ah[mt], sptr(gs->Ah[st]) + off);
            LDSM4(al[mt], sptr(gs->Al[st]) + off);
        }
        #pragma unroll
        for (int nt = 0; nt < 4; ++nt) {
            int k = lrow;
            int n = wn + nt * 8;
            uint32_t off = k * 256 + (((n >> 3) ^ (k & 7)) << 4);
            LDSMT2(bh[nt], sptr(gs->Bh[st]) + off);
            LDSMT2(bl[nt], sptr(gs->Bl[st]) + off);
        }
        #pragma unroll
        for (int mt = 0; mt < 4; ++mt)
            #pragma unroll
            for (int nt = 0; nt < 4; ++nt) {
                MMA16816(acc[mt][nt], ah[mt], bh[nt]);
                MMA16816(acc[mt][nt], ah[mt], bl[nt]);
                MMA16816(acc[mt][nt], al[mt], bh[nt]);
            }
        __syncthreads();
    }

    #pragma unroll
    for (int nt = 0; nt < 4; ++nt) {
        int cbase = n0 + wn + nt * 8 + 2 * (lane & 3);
        float2 bv = make_float2(0.f, 0.f);
        if (cbase + 1 < VOCAB) bv = *reinterpret_cast<const float2*>(bias + cbase);
        #pragma unroll
        for (int mt = 0; mt < 4; ++mt) {
            int r0 = m0 + wm + mt * 16 + (lane >> 2);
            if (cbase + 1 < VOCAB) {
                float2 v0 = make_float2(acc[mt][nt][0] + bv.x, acc[mt][nt][1] + bv.y);
                float2 v1 = make_float2(acc[mt][nt][2] + bv.x, acc[mt][nt][3] + bv.y);
                *reinterpret_cast<float2*>(C + (size_t)r0 * VOCAB + cbase) = v0;
                *reinterpret_cast<float2*>(C + (size_t)(r0 + 8) * VOCAB + cbase) = v1;
            }
        }
    }
}

// ================= fused kernel =================
__global__ __launch_bounds__(FTH, 1) __cluster_dims__(CLUSTER, 1, 1)
void fused_kernel(const int* __restrict__ X, const float* __restrict__ H0,
                  const float* __restrict__ Wxz, const float* __restrict__ Whz, const float* __restrict__ bz,
                  const float* __restrict__ Wxr, const float* __restrict__ Whr, const float* __restrict__ br,
                  const float* __restrict__ Wxh, const float* __restrict__ Whh, const float* __restrict__ bh,
                  const float* __restrict__ bq, float* __restrict__ C, float* __restrict__ outF)
{
    if (blockIdx.x < NREC) {
        rnn_body(X, H0, Wxz, Whz, bz, Wxr, Whr, br, Wxh, Whh, bh, outF);
    } else {
        gemm_body((int)blockIdx.x - NREC, bq, C);
    }
}

// ================= launch =================
extern "C" void kernel_launch(void* const* d_in, const int* in_sizes, int n_in,
                              void* d_out, int out_size) {
    const int*   X   = (const int*)  d_in[0];
    const float* H0  = (const float*)d_in[1];
    const float* Wxz = (const float*)d_in[2];
    const float* Whz = (const float*)d_in[3];
    const float* bz  = (const float*)d_in[4];
    const float* Wxr = (const float*)d_in[5];
    const float* Whr = (const float*)d_in[6];
    const float* br  = (const float*)d_in[7];
    const float* Wxh = (const float*)d_in[8];
    const float* Whh = (const float*)d_in[9];
    const float* bh  = (const float*)d_in[10];
    const float* Whq = (const float*)d_in[11];
    const float* bq  = (const float*)d_in[12];

    float* out  = (float*)d_out;
    float* outF = out + (out_size - BATCH * HID);

    static bool attr_set = false;
    if (!attr_set) {
        cudaFuncSetAttribute(fused_kernel, cudaFuncAttributeMaxDynamicSharedMemorySize,
                             (int)sizeof(RSmem));
        attr_set = true;
    }

    prog_reset_kernel<<<1, 64>>>();
    convB_kernel<<<(HID * VOCAB + 255) / 256, 256>>>(Whq);
    fused_kernel<<<NREC + NTM * NTN, FTH, sizeof(RSmem)>>>(
        X, H0, Wxz, Whz, bz, Wxr, Whr, br, Wxh, Whh, bh, bq, out, outF);
}